// round 11
// baseline (speedup 1.0000x reference)
#include <cuda_runtime.h>
#include <math.h>

#define NUx 128
#define MSx 64
#define DTx 128
#define Rx  4
#define INC 323      // inputs row stride: NU + MS + DT + 3
#define BMAX 4096

// ---------------- scratch (device globals: no allocation allowed) ----------
__device__ float g_hpt[BMAX * NUx];     // h_pre_tilde
__device__ float g_base[BMAX * NUx];    // per-b part of gate3 pre-activation
__device__ float g_lg[BMAX * NUx];      // learning gain
__device__ float g_preds[BMAX];         // preds (already /128)
__device__ float g_htilde[BMAX * NUx];  // corr . h
__device__ float g_S[3 * NUx];          // column sums of gate3_W rows 256..405

__device__ __forceinline__ float sigf(float x) { return 1.f / (1.f + __expf(-x)); }
__device__ __forceinline__ float gainf(float f) {
    return 0.3f + 0.7f / (1.f + __expf(-10.f * (f - 0.3f)));
}

#define LOAD16(dst, ptr) do {                                   \
    const float4* _p = (const float4*)(ptr);                    \
    float4 _a = _p[0], _b = _p[1], _c = _p[2], _d = _p[3];      \
    (dst)[0]=_a.x;(dst)[1]=_a.y;(dst)[2]=_a.z;(dst)[3]=_a.w;    \
    (dst)[4]=_b.x;(dst)[5]=_b.y;(dst)[6]=_b.z;(dst)[7]=_b.w;    \
    (dst)[8]=_c.x;(dst)[9]=_c.y;(dst)[10]=_c.z;(dst)[11]=_c.w;  \
    (dst)[12]=_d.x;(dst)[13]=_d.y;(dst)[14]=_d.z;(dst)[15]=_d.w;\
} while (0)

// ---------------- k0: fold the 3x50 broadcast rows of gate3_W --------------
__global__ void k0_sums(const float* __restrict__ g3W) {
    int n = threadIdx.x;  // 128 threads
    float s0 = 0.f, s1 = 0.f, s2 = 0.f;
#pragma unroll
    for (int u = 0; u < 50; u++) {
        s0 += g3W[(256 + u) * NUx + n];
        s1 += g3W[(306 + u) * NUx + n];
        s2 += g3W[(356 + u) * NUx + n];
    }
    g_S[n] = s0; g_S[NUx + n] = s1; g_S[2 * NUx + n] = s2;
}

// ---------------- k1: h_pre_tilde[b][n] = sum_m corr[m]*h_pre[m][n] --------
__global__ void k1_hpt(const float* __restrict__ inputs,
                       const float* __restrict__ states) {
    int b = blockIdx.x, n = threadIdx.x;  // 128 threads
    __shared__ float sc[MSx];
    if (n < MSx) sc[n] = inputs[(size_t)b * INC + NUx + n];
    __syncthreads();
    const float* hp = states + (size_t)b * MSx * NUx;
    float acc = 0.f;
#pragma unroll 8
    for (int m = 0; m < MSx; m++) acc += sc[m] * hp[(size_t)m * NUx + n];
    g_hpt[b * NUx + n] = acc;
}

// ---------------- k2: gates + preds + base + fusion (32-batch tiles) -------
// dynamic smem layout (floats):
//   sAT [384][32]  : A transposed -> rows 0..127 hpt, 128..255 interact, 256..383 topic
//   sGT [3][129][32]: gates transposed (row 128 = pad of ones)
//   sGain[32*3], sTAH[32*3], sPred[32]
#define K2_SMEM_FLOATS (12288 + 12384 + 96 + 96 + 32)

__global__ __launch_bounds__(256) void k2_gates(
    const float* __restrict__ inputs,
    const float* __restrict__ tgW, const float* __restrict__ tgb,
    const float* __restrict__ agW, const float* __restrict__ agb,
    const float* __restrict__ hgW, const float* __restrict__ hgb,
    const float* __restrict__ outW, const float* __restrict__ outb,
    const float* __restrict__ g3W, const float* __restrict__ g3b,
    const float* __restrict__ tW, const float* __restrict__ aW,
    const float* __restrict__ hW,
    const float* __restrict__ Wf, const float* __restrict__ bias) {
    extern __shared__ float sm[];
    float* sAT   = sm;              // 384*32
    float* sGT   = sm + 12288;      // 3*129*32
    float* sGain = sGT + 12384;
    float* sTAH  = sGain + 96;
    float* sPred = sTAH + 96;

    int tid = threadIdx.x;
    int b0 = blockIdx.x * 32;

    for (int idx = tid; idx < 32 * 128; idx += 256) {
        int i = idx >> 7, n = idx & 127;
        size_t ib = (size_t)(b0 + i);
        sAT[n * 32 + i]         = g_hpt[ib * NUx + n];
        sAT[(128 + n) * 32 + i] = inputs[ib * INC + n];          // interact
        sAT[(256 + n) * 32 + i] = inputs[ib * INC + 192 + n];    // topic
    }
    if (tid < 32) {
        size_t ib = (size_t)(b0 + tid);
        float t = inputs[ib * INC + 320];
        float a = inputs[ib * INC + 321];
        float h = inputs[ib * INC + 322];
        sTAH[tid * 3 + 0] = t; sTAH[tid * 3 + 1] = a; sTAH[tid * 3 + 2] = h;
        sGain[tid * 3 + 0] = gainf(t);
        sGain[tid * 3 + 1] = gainf(a);
        sGain[tid * 3 + 2] = gainf(h);
        sPred[tid] = 0.f;
    }
    if (tid < 96) {  // pad row (u = 128) of each gate = 1.0
        int g = tid / 32, i = tid % 32;
        sGT[g * 4128 + 128 * 32 + i] = 1.f;
    }
    __syncthreads();

    const int i2 = tid >> 7;        // 0/1
    const int n  = tid & 127;
    const int iBase = i2 * 16;

    // ---- pass A1: three gate matvecs, 16 batch rows per thread ----
    float zt[16], za[16], zh[16];
#pragma unroll
    for (int j = 0; j < 16; j++) { zt[j] = 0.f; za[j] = 0.f; zh[j] = 0.f; }
    for (int u = 0; u < 256; u++) {
        float wt = __ldg(tgW + u * NUx + n);
        float wa = __ldg(agW + u * NUx + n);
        float wh = __ldg(hgW + u * NUx + n);
        float xv[16];
        LOAD16(xv, sAT + u * 32 + iBase);
#pragma unroll
        for (int j = 0; j < 16; j++) {
            zt[j] += xv[j] * wt; za[j] += xv[j] * wa; zh[j] += xv[j] * wh;
        }
    }
    {
        float tb = tgb[n], ab = agb[n], hb = hgb[n];
#pragma unroll
        for (int j = 0; j < 16; j++) {
            int i = iBase + j;
            sGT[0 * 4128 + n * 32 + i] = sigf((zt[j] + tb) * sGain[i * 3 + 0]);
            sGT[1 * 4128 + n * 32 + i] = sigf((za[j] + ab) * sGain[i * 3 + 1]);
            sGT[2 * 4128 + n * 32 + i] = sigf((zh[j] + hb) * sGain[i * 3 + 2]);
        }
    }

    // ---- pass A2: out-layer pre-activation (preds) + gate3 per-b base ----
    float zp[16], zb[16];
#pragma unroll
    for (int j = 0; j < 16; j++) { zp[j] = 0.f; zb[j] = 0.f; }
    for (int u = 0; u < 128; u++) {
        float wp1 = __ldg(outW + u * NUx + n);           // hpt rows
        float wp2 = __ldg(outW + (128 + u) * NUx + n);   // topic rows
        float wb  = __ldg(g3W + (128 + u) * NUx + n);    // interact rows
        float xh[16], xi[16], xt[16];
        LOAD16(xh, sAT + u * 32 + iBase);
        LOAD16(xi, sAT + (128 + u) * 32 + iBase);
        LOAD16(xt, sAT + (256 + u) * 32 + iBase);
#pragma unroll
        for (int j = 0; j < 16; j++) {
            zp[j] += xh[j] * wp1 + xt[j] * wp2;
            zb[j] += xi[j] * wb;
        }
    }
    {
        float ob = outb[n], gb = g3b[n];
        float S0 = g_S[n], S1 = g_S[NUx + n], S2 = g_S[2 * NUx + n];
#pragma unroll
        for (int j = 0; j < 16; j++) {
            int i = iBase + j;
            size_t ib = (size_t)(b0 + i);
            g_base[ib * NUx + n] = zb[j] + gb + sTAH[i * 3 + 0] * S0 +
                                   sTAH[i * 3 + 1] * S1 + sTAH[i * 3 + 2] * S2;
            atomicAdd(&sPred[i], sigf(zp[j] + ob));
        }
    }
    __syncthreads();
    if (tid < 32) g_preds[b0 + tid] = sPred[tid] * (1.f / 128.f);

    // ---- pass B: fusion -> learning gain ----
    float lga[16];
#pragma unroll
    for (int j = 0; j < 16; j++) lga[j] = 0.f;
    for (int r = 0; r < 4; r++) {
        float ft[16], fa[16], fh[16];
#pragma unroll
        for (int j = 0; j < 16; j++) { ft[j] = 0.f; fa[j] = 0.f; fh[j] = 0.f; }
        for (int u = 0; u < 129; u++) {
            float wt = __ldg(tW + (r * 129 + u) * NUx + n);
            float wa = __ldg(aW + (r * 129 + u) * NUx + n);
            float wh = __ldg(hW + (r * 129 + u) * NUx + n);
            float tv[16], av[16], hv[16];
            LOAD16(tv, sGT + 0 * 4128 + u * 32 + iBase);
            LOAD16(av, sGT + 1 * 4128 + u * 32 + iBase);
            LOAD16(hv, sGT + 2 * 4128 + u * 32 + iBase);
#pragma unroll
            for (int j = 0; j < 16; j++) {
                ft[j] += tv[j] * wt; fa[j] += av[j] * wa; fh[j] += hv[j] * wh;
            }
        }
        float wfr = __ldg(Wf + r);
#pragma unroll
        for (int j = 0; j < 16; j++) lga[j] += wfr * ft[j] * fa[j] * fh[j];
    }
    {
        float bn = bias[n];
#pragma unroll
        for (int j = 0; j < 16; j++) {
            float v = lga[j] + bn;
            g_lg[(size_t)(b0 + iBase + j) * NUx + n] = v > 0.f ? v : 0.f;
        }
    }
}

// ---------------- k4: forget gate GEMM + h + h_tilde (one CTA per b) -------
__global__ __launch_bounds__(256) void k4_main(
    const float* __restrict__ inputs, const float* __restrict__ states,
    const float* __restrict__ g3W, float* __restrict__ out_h) {
    __shared__ __align__(16) float shT[128 * 68];  // [k][m] : h_pre transposed
    __shared__ float scorr[64];
    __shared__ float slg[128];
    __shared__ float sbase[128];
    __shared__ float spart[16 * 128];

    int tid = threadIdx.x, b = blockIdx.x;
    const float* hp = states + (size_t)b * MSx * NUx;
    for (int idx = tid; idx < MSx * NUx; idx += 256) {
        int m = idx >> 7, k = idx & 127;
        shT[k * 68 + m] = hp[idx];
    }
    if (tid < 64) scorr[tid] = inputs[(size_t)b * INC + NUx + tid];
    if (tid < 128) {
        slg[tid]   = g_lg[(size_t)b * NUx + tid];
        sbase[tid] = g_base[(size_t)b * NUx + tid];
    }
    __syncthreads();

    const int ty = tid >> 4, tx = tid & 15;
    const int m0 = ty * 4, n0 = tx * 8;

    float acc[4][8];
#pragma unroll
    for (int mi = 0; mi < 4; mi++)
#pragma unroll
        for (int nj = 0; nj < 8; nj++) acc[mi][nj] = sbase[n0 + nj];

    for (int k = 0; k < 128; k++) {
        float4 a4 = *(const float4*)(shT + k * 68 + m0);
        float4 w0 = __ldg((const float4*)(g3W + k * NUx + n0));
        float4 w1 = __ldg((const float4*)(g3W + k * NUx + n0 + 4));
        float am[4] = {a4.x, a4.y, a4.z, a4.w};
        float wn[8] = {w0.x, w0.y, w0.z, w0.w, w1.x, w1.y, w1.z, w1.w};
#pragma unroll
        for (int mi = 0; mi < 4; mi++)
#pragma unroll
            for (int nj = 0; nj < 8; nj++) acc[mi][nj] += am[mi] * wn[nj];
    }

    // epilogue: fg = sigmoid(acc); h = h_pre*fg + corr[m]*lg[n]
    float cr[4] = {scorr[m0], scorr[m0 + 1], scorr[m0 + 2], scorr[m0 + 3]};
    float lgv[8];
#pragma unroll
    for (int nj = 0; nj < 8; nj++) lgv[nj] = slg[n0 + nj];

    float hhf[8][4];
#pragma unroll
    for (int nj = 0; nj < 8; nj++) {
        float4 v = *(const float4*)(shT + (n0 + nj) * 68 + m0);
        hhf[nj][0] = v.x; hhf[nj][1] = v.y; hhf[nj][2] = v.z; hhf[nj][3] = v.w;
    }

    float pt[8];
#pragma unroll
    for (int nj = 0; nj < 8; nj++) pt[nj] = 0.f;

    float* ob = out_h + (size_t)b * MSx * NUx;
#pragma unroll
    for (int mi = 0; mi < 4; mi++) {
        float hv[8];
#pragma unroll
        for (int nj = 0; nj < 8; nj++) {
            float fg = sigf(acc[mi][nj]);
            float hval = hhf[nj][mi] * fg + cr[mi] * lgv[nj];
            hv[nj] = hval;
            pt[nj] += cr[mi] * hval;
        }
        float4 o0 = make_float4(hv[0], hv[1], hv[2], hv[3]);
        float4 o1 = make_float4(hv[4], hv[5], hv[6], hv[7]);
        *(float4*)(ob + (m0 + mi) * NUx + n0)     = o0;
        *(float4*)(ob + (m0 + mi) * NUx + n0 + 4) = o1;
    }
#pragma unroll
    for (int nj = 0; nj < 8; nj++) spart[ty * 128 + n0 + nj] = pt[nj];
    __syncthreads();
    if (tid < 128) {
        float s = 0.f;
#pragma unroll
        for (int t = 0; t < 16; t++) s += spart[t * 128 + tid];
        g_htilde[(size_t)b * NUx + tid] = s;
    }
}

// ---------------- k5: after_preds + improve -> result ----------------------
__global__ __launch_bounds__(256) void k5_result(
    const float* __restrict__ inputs, const float* __restrict__ outW,
    const float* __restrict__ outb, float* __restrict__ out) {
    __shared__ __align__(16) float sA[256 * 32];  // rows 0..127 htilde, 128..255 topic
    __shared__ float sAfter[32];
    int tid = threadIdx.x;
    int b0 = blockIdx.x * 32;
    for (int idx = tid; idx < 32 * 128; idx += 256) {
        int i = idx >> 7, n = idx & 127;
        size_t ib = (size_t)(b0 + i);
        sA[n * 32 + i]         = g_htilde[ib * NUx + n];
        sA[(128 + n) * 32 + i] = inputs[ib * INC + 192 + n];
    }
    if (tid < 32) sAfter[tid] = 0.f;
    __syncthreads();

    const int i2 = tid >> 7, n = tid & 127, iBase = i2 * 16;
    float zp[16];
#pragma unroll
    for (int j = 0; j < 16; j++) zp[j] = 0.f;
    for (int u = 0; u < 256; u++) {
        float w = __ldg(outW + u * NUx + n);
        float xv[16];
        LOAD16(xv, sA + u * 32 + iBase);
#pragma unroll
        for (int j = 0; j < 16; j++) zp[j] += xv[j] * w;
    }
    float ob = outb[n];
#pragma unroll
    for (int j = 0; j < 16; j++) atomicAdd(&sAfter[iBase + j], sigf(zp[j] + ob));
    __syncthreads();
    if (tid < 32) {
        int b = b0 + tid;
        float after = sAfter[tid] * (1.f / 128.f);
        float p = g_preds[b];
        out[2 * b]     = p;
        out[2 * b + 1] = (after - p) / (1.f - p);
    }
}

// ---------------- launch ----------------------------------------------------
extern "C" void kernel_launch(void* const* d_in, const int* in_sizes, int n_in,
                              void* d_out, int out_size) {
    const float* inputs = (const float*)d_in[0];
    const float* states = (const float*)d_in[1];
    const float* tW     = (const float*)d_in[2];
    const float* aW     = (const float*)d_in[3];
    const float* hW     = (const float*)d_in[4];
    const float* Wf     = (const float*)d_in[5];
    const float* bias   = (const float*)d_in[6];
    const float* g3W    = (const float*)d_in[7];
    const float* g3b    = (const float*)d_in[8];
    const float* outW   = (const float*)d_in[9];
    const float* outb   = (const float*)d_in[10];
    const float* tgW    = (const float*)d_in[11];
    const float* tgb    = (const float*)d_in[12];
    const float* agW    = (const float*)d_in[13];
    const float* agb    = (const float*)d_in[14];
    const float* hgW    = (const float*)d_in[15];
    const float* hgb    = (const float*)d_in[16];

    int B = in_sizes[0] / INC;  // 4096
    float* out   = (float*)d_out;
    float* out_h = out + (size_t)2 * B;  // (result, h) flattened in tuple order

    const int smem2 = K2_SMEM_FLOATS * (int)sizeof(float);
    cudaFuncSetAttribute(k2_gates, cudaFuncAttributeMaxDynamicSharedMemorySize, smem2);

    k0_sums<<<1, 128>>>(g3W);
    k1_hpt<<<B, 128>>>(inputs, states);
    k2_gates<<<B / 32, 256, smem2>>>(inputs, tgW, tgb, agW, agb, hgW, hgb,
                                     outW, outb, g3W, g3b, tW, aW, hW, Wf, bias);
    k4_main<<<B, 256>>>(inputs, states, g3W, out_h);
    k5_result<<<B / 32, 256>>>(inputs, outW, outb, out);
}

// round 12
// speedup vs baseline: 1.0012x; 1.0012x over previous
#include <cuda_runtime.h>
#include <math.h>

#define NUx 128
#define MSx 64
#define DTx 128
#define Rx  4
#define INC 323      // inputs row stride: NU + MS + DT + 3
#define BMAX 4096

// ---------------- scratch (device globals: no allocation allowed) ----------
__device__ float g_hpt[BMAX * NUx];     // h_pre_tilde
__device__ float g_base[BMAX * NUx];    // per-b part of gate3 pre-activation
__device__ float g_lg[BMAX * NUx];      // learning gain
__device__ float g_preds[BMAX];         // preds (already /128)
__device__ float g_htilde[BMAX * NUx];  // corr . h
__device__ float g_S[3 * NUx];          // column sums of gate3_W rows 256..405

__device__ __forceinline__ float sigf(float x) { return 1.f / (1.f + __expf(-x)); }
__device__ __forceinline__ float gainf(float f) {
    return 0.3f + 0.7f / (1.f + __expf(-10.f * (f - 0.3f)));
}

#define LOAD16(dst, ptr) do {                                   \
    const float4* _p = (const float4*)(ptr);                    \
    float4 _a = _p[0], _b = _p[1], _c = _p[2], _d = _p[3];      \
    (dst)[0]=_a.x;(dst)[1]=_a.y;(dst)[2]=_a.z;(dst)[3]=_a.w;    \
    (dst)[4]=_b.x;(dst)[5]=_b.y;(dst)[6]=_b.z;(dst)[7]=_b.w;    \
    (dst)[8]=_c.x;(dst)[9]=_c.y;(dst)[10]=_c.z;(dst)[11]=_c.w;  \
    (dst)[12]=_d.x;(dst)[13]=_d.y;(dst)[14]=_d.z;(dst)[15]=_d.w;\
} while (0)

// ---------------- k0: fold the 3x50 broadcast rows of gate3_W --------------
__global__ void k0_sums(const float* __restrict__ g3W) {
    int n = threadIdx.x;  // 128 threads
    float s0 = 0.f, s1 = 0.f, s2 = 0.f;
#pragma unroll
    for (int u = 0; u < 50; u++) {
        s0 += g3W[(256 + u) * NUx + n];
        s1 += g3W[(306 + u) * NUx + n];
        s2 += g3W[(356 + u) * NUx + n];
    }
    g_S[n] = s0; g_S[NUx + n] = s1; g_S[2 * NUx + n] = s2;
}

// ---------------- k1: h_pre_tilde[b][n] = sum_m corr[m]*h_pre[m][n] --------
__global__ void k1_hpt(const float* __restrict__ inputs,
                       const float* __restrict__ states) {
    int b = blockIdx.x, n = threadIdx.x;  // 128 threads
    __shared__ float sc[MSx];
    if (n < MSx) sc[n] = inputs[(size_t)b * INC + NUx + n];
    __syncthreads();
    const float* hp = states + (size_t)b * MSx * NUx;
    float acc = 0.f;
#pragma unroll 8
    for (int m = 0; m < MSx; m++) acc += sc[m] * hp[(size_t)m * NUx + n];
    g_hpt[b * NUx + n] = acc;
}

// ---------------- k2: gates + preds + base + fusion (32-batch tiles) -------
// dynamic smem layout (floats):
//   sAT [384][32]  : A transposed -> rows 0..127 hpt, 128..255 interact, 256..383 topic
//   sGT [3][129][32]: gates transposed (row 128 = pad of ones)
//   sGain[32*3], sTAH[32*3], sPred[32]
#define K2_SMEM_FLOATS (12288 + 12384 + 96 + 96 + 32)

__global__ __launch_bounds__(256) void k2_gates(
    const float* __restrict__ inputs,
    const float* __restrict__ tgW, const float* __restrict__ tgb,
    const float* __restrict__ agW, const float* __restrict__ agb,
    const float* __restrict__ hgW, const float* __restrict__ hgb,
    const float* __restrict__ outW, const float* __restrict__ outb,
    const float* __restrict__ g3W, const float* __restrict__ g3b,
    const float* __restrict__ tW, const float* __restrict__ aW,
    const float* __restrict__ hW,
    const float* __restrict__ Wf, const float* __restrict__ bias) {
    extern __shared__ float sm[];
    float* sAT   = sm;              // 384*32
    float* sGT   = sm + 12288;      // 3*129*32
    float* sGain = sGT + 12384;
    float* sTAH  = sGain + 96;
    float* sPred = sTAH + 96;

    int tid = threadIdx.x;
    int b0 = blockIdx.x * 32;

    for (int idx = tid; idx < 32 * 128; idx += 256) {
        int i = idx >> 7, n = idx & 127;
        size_t ib = (size_t)(b0 + i);
        sAT[n * 32 + i]         = g_hpt[ib * NUx + n];
        sAT[(128 + n) * 32 + i] = inputs[ib * INC + n];          // interact
        sAT[(256 + n) * 32 + i] = inputs[ib * INC + 192 + n];    // topic
    }
    if (tid < 32) {
        size_t ib = (size_t)(b0 + tid);
        float t = inputs[ib * INC + 320];
        float a = inputs[ib * INC + 321];
        float h = inputs[ib * INC + 322];
        sTAH[tid * 3 + 0] = t; sTAH[tid * 3 + 1] = a; sTAH[tid * 3 + 2] = h;
        sGain[tid * 3 + 0] = gainf(t);
        sGain[tid * 3 + 1] = gainf(a);
        sGain[tid * 3 + 2] = gainf(h);
        sPred[tid] = 0.f;
    }
    if (tid < 96) {  // pad row (u = 128) of each gate = 1.0
        int g = tid / 32, i = tid % 32;
        sGT[g * 4128 + 128 * 32 + i] = 1.f;
    }
    __syncthreads();

    const int i2 = tid >> 7;        // 0/1
    const int n  = tid & 127;
    const int iBase = i2 * 16;

    // ---- pass A1: three gate matvecs, 16 batch rows per thread ----
    float zt[16], za[16], zh[16];
#pragma unroll
    for (int j = 0; j < 16; j++) { zt[j] = 0.f; za[j] = 0.f; zh[j] = 0.f; }
    for (int u = 0; u < 256; u++) {
        float wt = __ldg(tgW + u * NUx + n);
        float wa = __ldg(agW + u * NUx + n);
        float wh = __ldg(hgW + u * NUx + n);
        float xv[16];
        LOAD16(xv, sAT + u * 32 + iBase);
#pragma unroll
        for (int j = 0; j < 16; j++) {
            zt[j] += xv[j] * wt; za[j] += xv[j] * wa; zh[j] += xv[j] * wh;
        }
    }
    {
        float tb = tgb[n], ab = agb[n], hb = hgb[n];
#pragma unroll
        for (int j = 0; j < 16; j++) {
            int i = iBase + j;
            sGT[0 * 4128 + n * 32 + i] = sigf((zt[j] + tb) * sGain[i * 3 + 0]);
            sGT[1 * 4128 + n * 32 + i] = sigf((za[j] + ab) * sGain[i * 3 + 1]);
            sGT[2 * 4128 + n * 32 + i] = sigf((zh[j] + hb) * sGain[i * 3 + 2]);
        }
    }

    // ---- pass A2: out-layer pre-activation (preds) + gate3 per-b base ----
    float zp[16], zb[16];
#pragma unroll
    for (int j = 0; j < 16; j++) { zp[j] = 0.f; zb[j] = 0.f; }
    for (int u = 0; u < 128; u++) {
        float wp1 = __ldg(outW + u * NUx + n);           // hpt rows
        float wp2 = __ldg(outW + (128 + u) * NUx + n);   // topic rows
        float wb  = __ldg(g3W + (128 + u) * NUx + n);    // interact rows
        float xh[16], xi[16], xt[16];
        LOAD16(xh, sAT + u * 32 + iBase);
        LOAD16(xi, sAT + (128 + u) * 32 + iBase);
        LOAD16(xt, sAT + (256 + u) * 32 + iBase);
#pragma unroll
        for (int j = 0; j < 16; j++) {
            zp[j] += xh[j] * wp1 + xt[j] * wp2;
            zb[j] += xi[j] * wb;
        }
    }
    {
        float ob = outb[n], gb = g3b[n];
        float S0 = g_S[n], S1 = g_S[NUx + n], S2 = g_S[2 * NUx + n];
#pragma unroll
        for (int j = 0; j < 16; j++) {
            int i = iBase + j;
            size_t ib = (size_t)(b0 + i);
            g_base[ib * NUx + n] = zb[j] + gb + sTAH[i * 3 + 0] * S0 +
                                   sTAH[i * 3 + 1] * S1 + sTAH[i * 3 + 2] * S2;
            atomicAdd(&sPred[i], sigf(zp[j] + ob));
        }
    }
    __syncthreads();
    if (tid < 32) g_preds[b0 + tid] = sPred[tid] * (1.f / 128.f);

    // ---- pass B: fusion -> learning gain ----
    float lga[16];
#pragma unroll
    for (int j = 0; j < 16; j++) lga[j] = 0.f;
    for (int r = 0; r < 4; r++) {
        float ft[16], fa[16], fh[16];
#pragma unroll
        for (int j = 0; j < 16; j++) { ft[j] = 0.f; fa[j] = 0.f; fh[j] = 0.f; }
        for (int u = 0; u < 129; u++) {
            float wt = __ldg(tW + (r * 129 + u) * NUx + n);
            float wa = __ldg(aW + (r * 129 + u) * NUx + n);
            float wh = __ldg(hW + (r * 129 + u) * NUx + n);
            float tv[16], av[16], hv[16];
            LOAD16(tv, sGT + 0 * 4128 + u * 32 + iBase);
            LOAD16(av, sGT + 1 * 4128 + u * 32 + iBase);
            LOAD16(hv, sGT + 2 * 4128 + u * 32 + iBase);
#pragma unroll
            for (int j = 0; j < 16; j++) {
                ft[j] += tv[j] * wt; fa[j] += av[j] * wa; fh[j] += hv[j] * wh;
            }
        }
        float wfr = __ldg(Wf + r);
#pragma unroll
        for (int j = 0; j < 16; j++) lga[j] += wfr * ft[j] * fa[j] * fh[j];
    }
    {
        float bn = bias[n];
#pragma unroll
        for (int j = 0; j < 16; j++) {
            float v = lga[j] + bn;
            g_lg[(size_t)(b0 + iBase + j) * NUx + n] = v > 0.f ? v : 0.f;
        }
    }
}

// ---------------- k4: forget gate GEMM + h + h_tilde (one CTA per b) -------
__global__ __launch_bounds__(256) void k4_main(
    const float* __restrict__ inputs, const float* __restrict__ states,
    const float* __restrict__ g3W, float* __restrict__ out_h) {
    __shared__ __align__(16) float shT[128 * 68];  // [k][m] : h_pre transposed
    __shared__ float scorr[64];
    __shared__ float slg[128];
    __shared__ float sbase[128];
    __shared__ float spart[16 * 128];

    int tid = threadIdx.x, b = blockIdx.x;
    const float* hp = states + (size_t)b * MSx * NUx;
    for (int idx = tid; idx < MSx * NUx; idx += 256) {
        int m = idx >> 7, k = idx & 127;
        shT[k * 68 + m] = hp[idx];
    }
    if (tid < 64) scorr[tid] = inputs[(size_t)b * INC + NUx + tid];
    if (tid < 128) {
        slg[tid]   = g_lg[(size_t)b * NUx + tid];
        sbase[tid] = g_base[(size_t)b * NUx + tid];
    }
    __syncthreads();

    const int ty = tid >> 4, tx = tid & 15;
    const int m0 = ty * 4, n0 = tx * 8;

    float acc[4][8];
#pragma unroll
    for (int mi = 0; mi < 4; mi++)
#pragma unroll
        for (int nj = 0; nj < 8; nj++) acc[mi][nj] = sbase[n0 + nj];

    for (int k = 0; k < 128; k++) {
        float4 a4 = *(const float4*)(shT + k * 68 + m0);
        float4 w0 = __ldg((const float4*)(g3W + k * NUx + n0));
        float4 w1 = __ldg((const float4*)(g3W + k * NUx + n0 + 4));
        float am[4] = {a4.x, a4.y, a4.z, a4.w};
        float wn[8] = {w0.x, w0.y, w0.z, w0.w, w1.x, w1.y, w1.z, w1.w};
#pragma unroll
        for (int mi = 0; mi < 4; mi++)
#pragma unroll
            for (int nj = 0; nj < 8; nj++) acc[mi][nj] += am[mi] * wn[nj];
    }

    // epilogue: fg = sigmoid(acc); h = h_pre*fg + corr[m]*lg[n]
    float cr[4] = {scorr[m0], scorr[m0 + 1], scorr[m0 + 2], scorr[m0 + 3]};
    float lgv[8];
#pragma unroll
    for (int nj = 0; nj < 8; nj++) lgv[nj] = slg[n0 + nj];

    float hhf[8][4];
#pragma unroll
    for (int nj = 0; nj < 8; nj++) {
        float4 v = *(const float4*)(shT + (n0 + nj) * 68 + m0);
        hhf[nj][0] = v.x; hhf[nj][1] = v.y; hhf[nj][2] = v.z; hhf[nj][3] = v.w;
    }

    float pt[8];
#pragma unroll
    for (int nj = 0; nj < 8; nj++) pt[nj] = 0.f;

    float* ob = out_h + (size_t)b * MSx * NUx;
#pragma unroll
    for (int mi = 0; mi < 4; mi++) {
        float hv[8];
#pragma unroll
        for (int nj = 0; nj < 8; nj++) {
            float fg = sigf(acc[mi][nj]);
            float hval = hhf[nj][mi] * fg + cr[mi] * lgv[nj];
            hv[nj] = hval;
            pt[nj] += cr[mi] * hval;
        }
        float4 o0 = make_float4(hv[0], hv[1], hv[2], hv[3]);
        float4 o1 = make_float4(hv[4], hv[5], hv[6], hv[7]);
        *(float4*)(ob + (m0 + mi) * NUx + n0)     = o0;
        *(float4*)(ob + (m0 + mi) * NUx + n0 + 4) = o1;
    }
#pragma unroll
    for (int nj = 0; nj < 8; nj++) spart[ty * 128 + n0 + nj] = pt[nj];
    __syncthreads();
    if (tid < 128) {
        float s = 0.f;
#pragma unroll
        for (int t = 0; t < 16; t++) s += spart[t * 128 + tid];
        g_htilde[(size_t)b * NUx + tid] = s;
    }
}

// ---------------- k5: after_preds + improve -> result ----------------------
__global__ __launch_bounds__(256) void k5_result(
    const float* __restrict__ inputs, const float* __restrict__ outW,
    const float* __restrict__ outb, float* __restrict__ out) {
    __shared__ __align__(16) float sA[256 * 32];  // rows 0..127 htilde, 128..255 topic
    __shared__ float sAfter[32];
    int tid = threadIdx.x;
    int b0 = blockIdx.x * 32;
    for (int idx = tid; idx < 32 * 128; idx += 256) {
        int i = idx >> 7, n = idx & 127;
        size_t ib = (size_t)(b0 + i);
        sA[n * 32 + i]         = g_htilde[ib * NUx + n];
        sA[(128 + n) * 32 + i] = inputs[ib * INC + 192 + n];
    }
    if (tid < 32) sAfter[tid] = 0.f;
    __syncthreads();

    const int i2 = tid >> 7, n = tid & 127, iBase = i2 * 16;
    float zp[16];
#pragma unroll
    for (int j = 0; j < 16; j++) zp[j] = 0.f;
    for (int u = 0; u < 256; u++) {
        float w = __ldg(outW + u * NUx + n);
        float xv[16];
        LOAD16(xv, sA + u * 32 + iBase);
#pragma unroll
        for (int j = 0; j < 16; j++) zp[j] += xv[j] * w;
    }
    float ob = outb[n];
#pragma unroll
    for (int j = 0; j < 16; j++) atomicAdd(&sAfter[iBase + j], sigf(zp[j] + ob));
    __syncthreads();
    if (tid < 32) {
        int b = b0 + tid;
        float after = sAfter[tid] * (1.f / 128.f);
        float p = g_preds[b];
        out[2 * b]     = p;
        out[2 * b + 1] = (after - p) / (1.f - p);
    }
}

// ---------------- launch ----------------------------------------------------
extern "C" void kernel_launch(void* const* d_in, const int* in_sizes, int n_in,
                              void* d_out, int out_size) {
    const float* inputs = (const float*)d_in[0];
    const float* states = (const float*)d_in[1];
    const float* tW     = (const float*)d_in[2];
    const float* aW     = (const float*)d_in[3];
    const float* hW     = (const float*)d_in[4];
    const float* Wf     = (const float*)d_in[5];
    const float* bias   = (const float*)d_in[6];
    const float* g3W    = (const float*)d_in[7];
    const float* g3b    = (const float*)d_in[8];
    const float* outW   = (const float*)d_in[9];
    const float* outb   = (const float*)d_in[10];
    const float* tgW    = (const float*)d_in[11];
    const float* tgb    = (const float*)d_in[12];
    const float* agW    = (const float*)d_in[13];
    const float* agb    = (const float*)d_in[14];
    const float* hgW    = (const float*)d_in[15];
    const float* hgb    = (const float*)d_in[16];

    int B = in_sizes[0] / INC;  // 4096
    float* out   = (float*)d_out;
    float* out_h = out + (size_t)2 * B;  // (result, h) flattened in tuple order

    const int smem2 = K2_SMEM_FLOATS * (int)sizeof(float);
    cudaFuncSetAttribute(k2_gates, cudaFuncAttributeMaxDynamicSharedMemorySize, smem2);

    k0_sums<<<1, 128>>>(g3W);
    k1_hpt<<<B, 128>>>(inputs, states);
    k2_gates<<<B / 32, 256, smem2>>>(inputs, tgW, tgb, agW, agb, hgW, hgb,
                                     outW, outb, g3W, g3b, tW, aW, hW, Wf, bias);
    k4_main<<<B, 256>>>(inputs, states, g3W, out_h);
    k5_result<<<B / 32, 256>>>(inputs, outW, outb, out);
}

// round 13
// speedup vs baseline: 1.8837x; 1.8815x over previous
#include <cuda_runtime.h>
#include <math.h>

#define NUx 128
#define MSx 64
#define INC 323      // inputs row stride: NU + MS + DT + 3
#define BMAX 4096
#define BN (BMAX * NUx)

typedef unsigned long long u64;

// ---------------- scratch (device globals: no allocation allowed) ----------
__device__ float g_hpt[BN];      // h_pre_tilde
__device__ float g_base[BN];     // per-b part of gate3 pre-activation
__device__ float g_lg[BN];       // learning gain
__device__ float g_preds[BMAX];  // preds (already /128)
__device__ float g_htilde[BN];   // corr . h
__device__ float g_S[3 * NUx];   // column sums of gate3_W rows 256..405
__device__ float g_gt[3 * BN];   // time/attempt/hint gates

__device__ __forceinline__ float sigf(float x) { return 1.f / (1.f + __expf(-x)); }
__device__ __forceinline__ float gainf(float f) {
    return 0.3f + 0.7f / (1.f + __expf(-10.f * (f - 0.3f)));
}

// ---- packed f32x2 helpers (sm_103a FFMA2) ----------------------------------
__device__ __forceinline__ u64 pk2(float lo, float hi) {
    u64 r; asm("mov.b64 %0, {%1, %2};" : "=l"(r) : "f"(lo), "f"(hi)); return r;
}
__device__ __forceinline__ float2 up2(u64 v) {
    float2 f; asm("mov.b64 {%0, %1}, %2;" : "=f"(f.x), "=f"(f.y) : "l"(v)); return f;
}
__device__ __forceinline__ u64 fma2(u64 a, u64 b, u64 c) {
    u64 d; asm("fma.rn.f32x2 %0, %1, %2, %3;" : "=l"(d) : "l"(a), "l"(b), "l"(c)); return d;
}

// ---------------- k0: fold the 3x50 broadcast rows of gate3_W --------------
__global__ void k0_sums(const float* __restrict__ g3W) {
    int n = threadIdx.x;  // 128 threads
    float s0 = 0.f, s1 = 0.f, s2 = 0.f;
#pragma unroll
    for (int u = 0; u < 50; u++) {
        s0 += g3W[(256 + u) * NUx + n];
        s1 += g3W[(306 + u) * NUx + n];
        s2 += g3W[(356 + u) * NUx + n];
    }
    g_S[n] = s0; g_S[NUx + n] = s1; g_S[2 * NUx + n] = s2;
}

// ---------------- k1: h_pre_tilde[b][n] = sum_m corr[m]*h_pre[m][n] --------
__global__ void k1_hpt(const float* __restrict__ inputs,
                       const float* __restrict__ states) {
    int b = blockIdx.x, n = threadIdx.x;  // 128 threads
    __shared__ float sc[MSx];
    if (n < MSx) sc[n] = inputs[(size_t)b * INC + NUx + n];
    __syncthreads();
    const float* hp = states + (size_t)b * MSx * NUx;
    float acc = 0.f;
#pragma unroll 8
    for (int m = 0; m < MSx; m++) acc += sc[m] * hp[(size_t)m * NUx + n];
    g_hpt[b * NUx + n] = acc;
}

// ---------------- k2a: 3 gate matvecs + preds + gate3 base (16-batch tiles) -
__global__ __launch_bounds__(256) void k2a_gates(
    const float* __restrict__ inputs,
    const float* __restrict__ tgW, const float* __restrict__ tgb,
    const float* __restrict__ agW, const float* __restrict__ agb,
    const float* __restrict__ hgW, const float* __restrict__ hgb,
    const float* __restrict__ outW, const float* __restrict__ outb,
    const float* __restrict__ g3W, const float* __restrict__ g3b) {
    __shared__ __align__(16) float sAT[384 * 16];  // rows: hpt, interact, topic
    __shared__ float sTAH[16 * 3];
    __shared__ float sGain[16 * 3];
    __shared__ float sPred[16];

    int tid = threadIdx.x;
    int b0 = blockIdx.x * 16;

    for (int idx = tid; idx < 16 * 128; idx += 256) {
        int i = idx >> 7, n = idx & 127;
        size_t ib = (size_t)(b0 + i);
        sAT[n * 16 + i]         = g_hpt[ib * NUx + n];
        sAT[(128 + n) * 16 + i] = inputs[ib * INC + n];
        sAT[(256 + n) * 16 + i] = inputs[ib * INC + 192 + n];
    }
    if (tid < 16) {
        size_t ib = (size_t)(b0 + tid);
        float t = inputs[ib * INC + 320];
        float a = inputs[ib * INC + 321];
        float h = inputs[ib * INC + 322];
        sTAH[tid * 3 + 0] = t; sTAH[tid * 3 + 1] = a; sTAH[tid * 3 + 2] = h;
        sGain[tid * 3 + 0] = gainf(t);
        sGain[tid * 3 + 1] = gainf(a);
        sGain[tid * 3 + 2] = gainf(h);
        sPred[tid] = 0.f;
    }
    __syncthreads();

    const int i2 = tid >> 7;     // 0/1
    const int n  = tid & 127;
    const int iB = i2 * 8;

    // ---- pass A1: three gate matvecs (8 batch rows per thread, f32x2) ----
    u64 zt[4] = {0,0,0,0}, za[4] = {0,0,0,0}, zh[4] = {0,0,0,0};
#pragma unroll 2
    for (int u = 0; u < 256; u++) {
        float wt = __ldg(tgW + u * NUx + n);
        float wa = __ldg(agW + u * NUx + n);
        float wh = __ldg(hgW + u * NUx + n);
        u64 wt2 = pk2(wt, wt), wa2 = pk2(wa, wa), wh2 = pk2(wh, wh);
        const ulonglong2* xp = (const ulonglong2*)(sAT + u * 16 + iB);
        ulonglong2 x01 = xp[0], x23 = xp[1];
        u64 xv[4] = {x01.x, x01.y, x23.x, x23.y};
#pragma unroll
        for (int p = 0; p < 4; p++) {
            zt[p] = fma2(xv[p], wt2, zt[p]);
            za[p] = fma2(xv[p], wa2, za[p]);
            zh[p] = fma2(xv[p], wh2, zh[p]);
        }
    }
    {
        float tb = __ldg(tgb + n), ab = __ldg(agb + n), hb = __ldg(hgb + n);
#pragma unroll
        for (int p = 0; p < 4; p++) {
            float2 t = up2(zt[p]), a = up2(za[p]), h = up2(zh[p]);
            int i0 = iB + 2 * p, i1 = i0 + 1;
            size_t r0 = (size_t)(b0 + i0) * NUx + n;
            size_t r1 = (size_t)(b0 + i1) * NUx + n;
            g_gt[r0]          = sigf((t.x + tb) * sGain[i0 * 3 + 0]);
            g_gt[r1]          = sigf((t.y + tb) * sGain[i1 * 3 + 0]);
            g_gt[BN + r0]     = sigf((a.x + ab) * sGain[i0 * 3 + 1]);
            g_gt[BN + r1]     = sigf((a.y + ab) * sGain[i1 * 3 + 1]);
            g_gt[2 * BN + r0] = sigf((h.x + hb) * sGain[i0 * 3 + 2]);
            g_gt[2 * BN + r1] = sigf((h.y + hb) * sGain[i1 * 3 + 2]);
        }
    }

    // ---- pass A2: preds pre-activation + gate3 per-b base ----
    u64 zp[4] = {0,0,0,0}, zb[4] = {0,0,0,0};
#pragma unroll 2
    for (int u = 0; u < 128; u++) {
        float wp1 = __ldg(outW + u * NUx + n);
        float wp2 = __ldg(outW + (128 + u) * NUx + n);
        float wb  = __ldg(g3W + (128 + u) * NUx + n);
        u64 wp12 = pk2(wp1, wp1), wp22 = pk2(wp2, wp2), wb2 = pk2(wb, wb);
        const ulonglong2* xhp = (const ulonglong2*)(sAT + u * 16 + iB);
        const ulonglong2* xip = (const ulonglong2*)(sAT + (128 + u) * 16 + iB);
        const ulonglong2* xtp = (const ulonglong2*)(sAT + (256 + u) * 16 + iB);
        ulonglong2 h01 = xhp[0], h23 = xhp[1];
        ulonglong2 i01 = xip[0], i23 = xip[1];
        ulonglong2 t01 = xtp[0], t23 = xtp[1];
        u64 xh[4] = {h01.x, h01.y, h23.x, h23.y};
        u64 xi[4] = {i01.x, i01.y, i23.x, i23.y};
        u64 xt[4] = {t01.x, t01.y, t23.x, t23.y};
#pragma unroll
        for (int p = 0; p < 4; p++) {
            zp[p] = fma2(xh[p], wp12, zp[p]);
            zp[p] = fma2(xt[p], wp22, zp[p]);
            zb[p] = fma2(xi[p], wb2,  zb[p]);
        }
    }
    {
        float ob = __ldg(outb + n), gb = __ldg(g3b + n);
        float S0 = g_S[n], S1 = g_S[NUx + n], S2 = g_S[2 * NUx + n];
#pragma unroll
        for (int p = 0; p < 4; p++) {
            float2 P = up2(zp[p]), Bv = up2(zb[p]);
            int i0 = iB + 2 * p, i1 = i0 + 1;
            size_t r0 = (size_t)(b0 + i0) * NUx + n;
            size_t r1 = (size_t)(b0 + i1) * NUx + n;
            g_base[r0] = Bv.x + gb + sTAH[i0*3+0]*S0 + sTAH[i0*3+1]*S1 + sTAH[i0*3+2]*S2;
            g_base[r1] = Bv.y + gb + sTAH[i1*3+0]*S0 + sTAH[i1*3+1]*S1 + sTAH[i1*3+2]*S2;
            atomicAdd(&sPred[i0], sigf(P.x + ob));
            atomicAdd(&sPred[i1], sigf(P.y + ob));
        }
    }
    __syncthreads();
    if (tid < 16) g_preds[b0 + tid] = sPred[tid] * (1.f / 128.f);
}

// ---------------- k2b: R=4 three-way fusion -> learning gain ---------------
__global__ __launch_bounds__(256) void k2b_fusion(
    const float* __restrict__ tW, const float* __restrict__ aW,
    const float* __restrict__ hW,
    const float* __restrict__ Wf, const float* __restrict__ bias) {
    __shared__ __align__(16) float sGT[3 * 128 * 16];  // 24 KB, gates transposed
    int tid = threadIdx.x;
    int b0 = blockIdx.x * 16;

    for (int idx = tid; idx < 16 * 128; idx += 256) {
        int i = idx >> 7, n = idx & 127;
        size_t src = (size_t)(b0 + i) * NUx + n;
        sGT[n * 16 + i]              = g_gt[src];
        sGT[2048 + n * 16 + i]       = g_gt[BN + src];
        sGT[2 * 2048 + n * 16 + i]   = g_gt[2 * BN + src];
    }
    __syncthreads();

    const int i2 = tid >> 7, n = tid & 127, iB = i2 * 8;

    float lga[8] = {0,0,0,0,0,0,0,0};
#pragma unroll 1
    for (int r = 0; r < 4; r++) {
        const float* tWr = tW + (size_t)r * 129 * NUx;
        const float* aWr = aW + (size_t)r * 129 * NUx;
        const float* hWr = hW + (size_t)r * 129 * NUx;
        u64 ft[4] = {0,0,0,0}, fa[4] = {0,0,0,0}, fh[4] = {0,0,0,0};
#pragma unroll 2
        for (int u = 0; u < 128; u++) {
            float wt = __ldg(tWr + u * NUx + n);
            float wa = __ldg(aWr + u * NUx + n);
            float wh = __ldg(hWr + u * NUx + n);
            u64 wt2 = pk2(wt, wt), wa2 = pk2(wa, wa), wh2 = pk2(wh, wh);
            const ulonglong2* tp = (const ulonglong2*)(sGT + u * 16 + iB);
            const ulonglong2* ap = (const ulonglong2*)(sGT + 2048 + u * 16 + iB);
            const ulonglong2* hp = (const ulonglong2*)(sGT + 2 * 2048 + u * 16 + iB);
            ulonglong2 t01 = tp[0], t23 = tp[1];
            ulonglong2 a01 = ap[0], a23 = ap[1];
            ulonglong2 h01 = hp[0], h23 = hp[1];
            u64 xt[4] = {t01.x, t01.y, t23.x, t23.y};
            u64 xa[4] = {a01.x, a01.y, a23.x, a23.y};
            u64 xh[4] = {h01.x, h01.y, h23.x, h23.y};
#pragma unroll
            for (int p = 0; p < 4; p++) {
                ft[p] = fma2(xt[p], wt2, ft[p]);
                fa[p] = fma2(xa[p], wa2, fa[p]);
                fh[p] = fma2(xh[p], wh2, fh[p]);
            }
        }
        // pad row (gate value 1.0): adds W[r][128][n]
        float padT = __ldg(tWr + 128 * NUx + n);
        float padA = __ldg(aWr + 128 * NUx + n);
        float padH = __ldg(hWr + 128 * NUx + n);
        float wfr  = __ldg(Wf + r);
#pragma unroll
        for (int p = 0; p < 4; p++) {
            float2 t = up2(ft[p]), a = up2(fa[p]), h = up2(fh[p]);
            lga[2*p]   += wfr * (t.x + padT) * (a.x + padA) * (h.x + padH);
            lga[2*p+1] += wfr * (t.y + padT) * (a.y + padA) * (h.y + padH);
        }
    }
    float bn = __ldg(bias + n);
#pragma unroll
    for (int j = 0; j < 8; j++) {
        float v = lga[j] + bn;
        g_lg[(size_t)(b0 + iB + j) * NUx + n] = v > 0.f ? v : 0.f;
    }
}

// ---------------- k4: forget gate GEMM + h + h_tilde (one CTA per b) -------
// smem: sW (g3W rows 0..127) 64KB + sH (h_pre) 32KB + spart 8KB + misc
__global__ __launch_bounds__(256) void k4_main(
    const float* __restrict__ inputs, const float* __restrict__ states,
    const float* __restrict__ g3W, float* __restrict__ out_h) {
    extern __shared__ float sm4[];
    float* sW    = sm4;            // 128*128
    float* sH    = sm4 + 16384;    // 64*128  (natural [m][k])
    float* spart = sH + 8192;      // 16*128
    float* scorr = spart + 2048;   // 64
    float* slg   = scorr + 64;     // 128
    float* sbase = slg + 128;      // 128

    int tid = threadIdx.x, b = blockIdx.x;
    for (int idx = tid * 4; idx < 16384; idx += 1024)
        *(float4*)(sW + idx) = __ldg((const float4*)(g3W + idx));
    const float* hp = states + (size_t)b * MSx * NUx;
    for (int idx = tid * 4; idx < 8192; idx += 1024)
        *(float4*)(sH + idx) = *(const float4*)(hp + idx);
    if (tid < 64) scorr[tid] = inputs[(size_t)b * INC + NUx + tid];
    if (tid < 128) {
        slg[tid]   = g_lg[(size_t)b * NUx + tid];
        sbase[tid] = g_base[(size_t)b * NUx + tid];
    }
    __syncthreads();

    const int ty = tid >> 4, tx = tid & 15;
    const int m0 = ty * 4;
    const int na = tx * 4, nb = 64 + tx * 4;   // conflict-free LDS phases

    u64 base2[4] = { pk2(sbase[na], sbase[na+1]), pk2(sbase[na+2], sbase[na+3]),
                     pk2(sbase[nb], sbase[nb+1]), pk2(sbase[nb+2], sbase[nb+3]) };
    u64 acc[4][4];
#pragma unroll
    for (int mi = 0; mi < 4; mi++)
#pragma unroll
        for (int p = 0; p < 4; p++) acc[mi][p] = base2[p];

#pragma unroll 4
    for (int k = 0; k < 128; k++) {
        ulonglong2 w0 = *(const ulonglong2*)(sW + k * NUx + na);
        ulonglong2 w1 = *(const ulonglong2*)(sW + k * NUx + nb);
        u64 wv[4] = {w0.x, w0.y, w1.x, w1.y};
#pragma unroll
        for (int mi = 0; mi < 4; mi++) {
            float a = sH[(m0 + mi) * NUx + k];
            u64 aa = pk2(a, a);
#pragma unroll
            for (int p = 0; p < 4; p++) acc[mi][p] = fma2(aa, wv[p], acc[mi][p]);
        }
    }

    // epilogue: fg = sigmoid(acc); h = h_pre*fg + corr[m]*lg[n]; reduce corr.h
    float cr[4] = {scorr[m0], scorr[m0+1], scorr[m0+2], scorr[m0+3]};
    float lgv[8] = {slg[na], slg[na+1], slg[na+2], slg[na+3],
                    slg[nb], slg[nb+1], slg[nb+2], slg[nb+3]};
    float pt[8] = {0,0,0,0,0,0,0,0};
    float* ob = out_h + (size_t)b * MSx * NUx;

#pragma unroll
    for (int mi = 0; mi < 4; mi++) {
        float4 ha = *(const float4*)(sH + (m0 + mi) * NUx + na);
        float4 hb4 = *(const float4*)(sH + (m0 + mi) * NUx + nb);
        float hpv[8] = {ha.x, ha.y, ha.z, ha.w, hb4.x, hb4.y, hb4.z, hb4.w};
        float z[8];
#pragma unroll
        for (int p = 0; p < 4; p++) {
            float2 f = up2(acc[mi][p]);
            z[2*p] = f.x; z[2*p+1] = f.y;
        }
        float hv[8];
#pragma unroll
        for (int q = 0; q < 8; q++) {
            float fg = sigf(z[q]);
            hv[q] = hpv[q] * fg + cr[mi] * lgv[q];
            pt[q] += cr[mi] * hv[q];
        }
        *(float4*)(ob + (m0 + mi) * NUx + na) = make_float4(hv[0], hv[1], hv[2], hv[3]);
        *(float4*)(ob + (m0 + mi) * NUx + nb) = make_float4(hv[4], hv[5], hv[6], hv[7]);
    }
#pragma unroll
    for (int q = 0; q < 4; q++) {
        spart[ty * NUx + na + q] = pt[q];
        spart[ty * NUx + nb + q] = pt[4 + q];
    }
    __syncthreads();
    if (tid < 128) {
        float s = 0.f;
#pragma unroll
        for (int t = 0; t < 16; t++) s += spart[t * NUx + tid];
        g_htilde[(size_t)b * NUx + tid] = s;
    }
}

// ---------------- k5: after_preds + improve -> result ----------------------
__global__ __launch_bounds__(256) void k5_result(
    const float* __restrict__ inputs, const float* __restrict__ outW,
    const float* __restrict__ outb, float* __restrict__ out) {
    __shared__ __align__(16) float sA[256 * 16];  // rows 0..127 htilde, 128..255 topic
    __shared__ float sAfter[16];
    int tid = threadIdx.x;
    int b0 = blockIdx.x * 16;
    for (int idx = tid; idx < 16 * 128; idx += 256) {
        int i = idx >> 7, n = idx & 127;
        size_t ib = (size_t)(b0 + i);
        sA[n * 16 + i]         = g_htilde[ib * NUx + n];
        sA[(128 + n) * 16 + i] = inputs[ib * INC + 192 + n];
    }
    if (tid < 16) sAfter[tid] = 0.f;
    __syncthreads();

    const int i2 = tid >> 7, n = tid & 127, iB = i2 * 8;
    u64 zp[4] = {0,0,0,0};
#pragma unroll 2
    for (int u = 0; u < 256; u++) {
        float w = __ldg(outW + u * NUx + n);
        u64 w2 = pk2(w, w);
        const ulonglong2* xp = (const ulonglong2*)(sA + u * 16 + iB);
        ulonglong2 x01 = xp[0], x23 = xp[1];
        zp[0] = fma2(x01.x, w2, zp[0]);
        zp[1] = fma2(x01.y, w2, zp[1]);
        zp[2] = fma2(x23.x, w2, zp[2]);
        zp[3] = fma2(x23.y, w2, zp[3]);
    }
    float ob = __ldg(outb + n);
#pragma unroll
    for (int p = 0; p < 4; p++) {
        float2 P = up2(zp[p]);
        atomicAdd(&sAfter[iB + 2*p],     sigf(P.x + ob));
        atomicAdd(&sAfter[iB + 2*p + 1], sigf(P.y + ob));
    }
    __syncthreads();
    if (tid < 16) {
        int b = b0 + tid;
        float after = sAfter[tid] * (1.f / 128.f);
        float p = g_preds[b];
        out[2 * b]     = p;
        out[2 * b + 1] = (after - p) / (1.f - p);
    }
}

// ---------------- launch ----------------------------------------------------
extern "C" void kernel_launch(void* const* d_in, const int* in_sizes, int n_in,
                              void* d_out, int out_size) {
    const float* inputs = (const float*)d_in[0];
    const float* states = (const float*)d_in[1];
    const float* tW     = (const float*)d_in[2];
    const float* aW     = (const float*)d_in[3];
    const float* hW     = (const float*)d_in[4];
    const float* Wf     = (const float*)d_in[5];
    const float* bias   = (const float*)d_in[6];
    const float* g3W    = (const float*)d_in[7];
    const float* g3b    = (const float*)d_in[8];
    const float* outW   = (const float*)d_in[9];
    const float* outb   = (const float*)d_in[10];
    const float* tgW    = (const float*)d_in[11];
    const float* tgb    = (const float*)d_in[12];
    const float* agW    = (const float*)d_in[13];
    const float* agb    = (const float*)d_in[14];
    const float* hgW    = (const float*)d_in[15];
    const float* hgb    = (const float*)d_in[16];

    int B = in_sizes[0] / INC;  // 4096
    float* out   = (float*)d_out;
    float* out_h = out + (size_t)2 * B;  // (result, h) flattened in tuple order

    const int smem4 = (16384 + 8192 + 2048 + 64 + 128 + 128) * (int)sizeof(float);
    cudaFuncSetAttribute(k4_main, cudaFuncAttributeMaxDynamicSharedMemorySize, smem4);

    k0_sums<<<1, 128>>>(g3W);
    k1_hpt<<<B, 128>>>(inputs, states);
    k2a_gates<<<B / 16, 256>>>(inputs, tgW, tgb, agW, agb, hgW, hgb,
                               outW, outb, g3W, g3b);
    k2b_fusion<<<B / 16, 256>>>(tW, aW, hW, Wf, bias);
    k4_main<<<B, 256, smem4>>>(inputs, states, g3W, out_h);
    k5_result<<<B / 16, 256>>>(inputs, outW, outb, out);
}

// round 14
// speedup vs baseline: 2.4463x; 1.2987x over previous
#include <cuda_runtime.h>
#include <math.h>

#define NUx 128
#define MSx 64
#define INC 323      // inputs row stride: NU + MS + DT + 3
#define BMAX 4096
#define BN (BMAX * NUx)

typedef unsigned long long u64;

// ---------------- scratch (device globals: no allocation allowed) ----------
__device__ float g_hpt[BN];      // h_pre_tilde
__device__ float g_base[BN];     // per-b part of gate3 pre-activation
__device__ float g_lg[BN];       // learning gain
__device__ float g_preds[BMAX];  // preds (already /128)
__device__ float g_htilde[BN];   // corr . h
__device__ float g_S[3 * NUx];   // column sums of gate3_W rows 256..405

__device__ __forceinline__ float sigf(float x) { return 1.f / (1.f + __expf(-x)); }
__device__ __forceinline__ float gainf(float f) {
    return 0.3f + 0.7f / (1.f + __expf(-10.f * (f - 0.3f)));
}

// ---- packed f32x2 helpers (sm_103a FFMA2) ----------------------------------
__device__ __forceinline__ u64 pk2(float lo, float hi) {
    u64 r; asm("mov.b64 %0, {%1, %2};" : "=l"(r) : "f"(lo), "f"(hi)); return r;
}
__device__ __forceinline__ float2 up2(u64 v) {
    float2 f; asm("mov.b64 {%0, %1}, %2;" : "=f"(f.x), "=f"(f.y) : "l"(v)); return f;
}
__device__ __forceinline__ u64 fma2(u64 a, u64 b, u64 c) {
    u64 d; asm("fma.rn.f32x2 %0, %1, %2, %3;" : "=l"(d) : "l"(a), "l"(b), "l"(c)); return d;
}

// ---------------- k0: fold the 3x50 broadcast rows of gate3_W --------------
__global__ void k0_sums(const float* __restrict__ g3W) {
    int n = threadIdx.x;  // 128 threads
    float s0 = 0.f, s1 = 0.f, s2 = 0.f;
#pragma unroll
    for (int u = 0; u < 50; u++) {
        s0 += g3W[(256 + u) * NUx + n];
        s1 += g3W[(306 + u) * NUx + n];
        s2 += g3W[(356 + u) * NUx + n];
    }
    g_S[n] = s0; g_S[NUx + n] = s1; g_S[2 * NUx + n] = s2;
}

// ---------------- k1: h_pre_tilde[b][n] = sum_m corr[m]*h_pre[m][n] --------
__global__ __launch_bounds__(256) void k1_hpt(const float* __restrict__ inputs,
                                              const float* __restrict__ states) {
    int b = blockIdx.x;
    int tid = threadIdx.x;
    int n = tid & 127, half = tid >> 7;  // half in {0,1}, m-range of 32
    __shared__ float sc[MSx];
    __shared__ float sp[2 * NUx];
    if (tid < MSx) sc[tid] = inputs[(size_t)b * INC + NUx + tid];
    __syncthreads();
    const float* hp = states + (size_t)b * MSx * NUx + (size_t)half * 32 * NUx;
    const float* cm = sc + half * 32;
    float acc = 0.f;
#pragma unroll 8
    for (int m = 0; m < 32; m++) acc += cm[m] * hp[(size_t)m * NUx + n];
    sp[half * NUx + n] = acc;
    __syncthreads();
    if (tid < NUx) g_hpt[(size_t)b * NUx + tid] = sp[tid] + sp[NUx + tid];
}

// ---------------- k2: gates + preds + base + fusion (16-batch, 512 thr) ----
// dyn smem floats: sAT 384*16 | sGT 3*128*16 | sTAH 48 | sGain 48 | sPred 16
#define K2_SMEM_FLOATS (6144 + 6144 + 48 + 48 + 16)

__global__ __launch_bounds__(512) void k2_gates(
    const float* __restrict__ inputs,
    const float* __restrict__ tgW, const float* __restrict__ tgb,
    const float* __restrict__ agW, const float* __restrict__ agb,
    const float* __restrict__ hgW, const float* __restrict__ hgb,
    const float* __restrict__ outW, const float* __restrict__ outb,
    const float* __restrict__ g3W, const float* __restrict__ g3b,
    const float* __restrict__ tW, const float* __restrict__ aW,
    const float* __restrict__ hW,
    const float* __restrict__ Wf, const float* __restrict__ bias) {
    extern __shared__ float sm[];
    float* sAT   = sm;             // [384][16]
    float* sGT   = sm + 6144;      // [3][128][16]
    float* sTAH  = sGT + 6144;     // [16][3]
    float* sGain = sTAH + 48;      // [16][3]
    float* sPred = sGain + 48;     // [16]

    int tid = threadIdx.x;
    int b0 = blockIdx.x * 16;

    for (int idx = tid; idx < 16 * 128; idx += 512) {
        int i = idx >> 7, n = idx & 127;
        size_t ib = (size_t)(b0 + i);
        sAT[n * 16 + i]         = g_hpt[ib * NUx + n];
        sAT[(128 + n) * 16 + i] = inputs[ib * INC + n];
        sAT[(256 + n) * 16 + i] = inputs[ib * INC + 192 + n];
    }
    if (tid < 16) {
        size_t ib = (size_t)(b0 + tid);
        float t = inputs[ib * INC + 320];
        float a = inputs[ib * INC + 321];
        float h = inputs[ib * INC + 322];
        sTAH[tid * 3 + 0] = t; sTAH[tid * 3 + 1] = a; sTAH[tid * 3 + 2] = h;
        sGain[tid * 3 + 0] = gainf(t);
        sGain[tid * 3 + 1] = gainf(a);
        sGain[tid * 3 + 2] = gainf(h);
        sPred[tid] = 0.f;
    }
    __syncthreads();

    const int i2 = tid >> 7;      // 0..3
    const int n  = tid & 127;
    const int iB = i2 * 4;        // 4 batch rows per thread

    // ---- pass A1: three gate matvecs (f32x2, 4 rows/thread) ----
    u64 zt[2] = {0,0}, za[2] = {0,0}, zh[2] = {0,0};
#pragma unroll 4
    for (int u = 0; u < 256; u++) {
        float wt = __ldg(tgW + u * NUx + n);
        float wa = __ldg(agW + u * NUx + n);
        float wh = __ldg(hgW + u * NUx + n);
        u64 wt2 = pk2(wt, wt), wa2 = pk2(wa, wa), wh2 = pk2(wh, wh);
        ulonglong2 x = *(const ulonglong2*)(sAT + u * 16 + iB);
        zt[0] = fma2(x.x, wt2, zt[0]); zt[1] = fma2(x.y, wt2, zt[1]);
        za[0] = fma2(x.x, wa2, za[0]); za[1] = fma2(x.y, wa2, za[1]);
        zh[0] = fma2(x.x, wh2, zh[0]); zh[1] = fma2(x.y, wh2, zh[1]);
    }
    {
        float tb = __ldg(tgb + n), ab = __ldg(agb + n), hb = __ldg(hgb + n);
#pragma unroll
        for (int p = 0; p < 2; p++) {
            float2 t = up2(zt[p]), a = up2(za[p]), h = up2(zh[p]);
            int i0 = iB + 2 * p, i1 = i0 + 1;
            sGT[n * 16 + i0]            = sigf((t.x + tb) * sGain[i0 * 3 + 0]);
            sGT[n * 16 + i1]            = sigf((t.y + tb) * sGain[i1 * 3 + 0]);
            sGT[2048 + n * 16 + i0]     = sigf((a.x + ab) * sGain[i0 * 3 + 1]);
            sGT[2048 + n * 16 + i1]     = sigf((a.y + ab) * sGain[i1 * 3 + 1]);
            sGT[2 * 2048 + n * 16 + i0] = sigf((h.x + hb) * sGain[i0 * 3 + 2]);
            sGT[2 * 2048 + n * 16 + i1] = sigf((h.y + hb) * sGain[i1 * 3 + 2]);
        }
    }

    // ---- pass A2: preds pre-activation + gate3 per-b base ----
    u64 zp[2] = {0,0}, zb[2] = {0,0};
#pragma unroll 4
    for (int u = 0; u < 128; u++) {
        float wp1 = __ldg(outW + u * NUx + n);
        float wp2 = __ldg(outW + (128 + u) * NUx + n);
        float wb  = __ldg(g3W + (128 + u) * NUx + n);
        u64 wp12 = pk2(wp1, wp1), wp22 = pk2(wp2, wp2), wb2 = pk2(wb, wb);
        ulonglong2 xh = *(const ulonglong2*)(sAT + u * 16 + iB);
        ulonglong2 xi = *(const ulonglong2*)(sAT + (128 + u) * 16 + iB);
        ulonglong2 xt = *(const ulonglong2*)(sAT + (256 + u) * 16 + iB);
        zp[0] = fma2(xh.x, wp12, zp[0]); zp[1] = fma2(xh.y, wp12, zp[1]);
        zp[0] = fma2(xt.x, wp22, zp[0]); zp[1] = fma2(xt.y, wp22, zp[1]);
        zb[0] = fma2(xi.x, wb2,  zb[0]); zb[1] = fma2(xi.y, wb2,  zb[1]);
    }
    {
        float ob = __ldg(outb + n), gb = __ldg(g3b + n);
        float S0 = g_S[n], S1 = g_S[NUx + n], S2 = g_S[2 * NUx + n];
        float pj[4];
#pragma unroll
        for (int p = 0; p < 2; p++) {
            float2 P = up2(zp[p]), Bv = up2(zb[p]);
            int i0 = iB + 2 * p, i1 = i0 + 1;
            size_t r0 = (size_t)(b0 + i0) * NUx + n;
            size_t r1 = (size_t)(b0 + i1) * NUx + n;
            g_base[r0] = Bv.x + gb + sTAH[i0*3+0]*S0 + sTAH[i0*3+1]*S1 + sTAH[i0*3+2]*S2;
            g_base[r1] = Bv.y + gb + sTAH[i1*3+0]*S0 + sTAH[i1*3+1]*S1 + sTAH[i1*3+2]*S2;
            pj[2*p]   = sigf(P.x + ob);
            pj[2*p+1] = sigf(P.y + ob);
        }
        // warp-level reduce over the 32 n's in this warp, then 1 atomic/warp/j
#pragma unroll
        for (int j = 0; j < 4; j++) {
            float v = pj[j];
#pragma unroll
            for (int off = 16; off > 0; off >>= 1)
                v += __shfl_xor_sync(0xFFFFFFFFu, v, off);
            if ((tid & 31) == 0) atomicAdd(&sPred[iB + j], v);
        }
    }
    __syncthreads();
    if (tid < 16) g_preds[b0 + tid] = sPred[tid] * (1.f / 128.f);

    // ---- pass B: R=4 three-way fusion -> learning gain ----
    float lga[4] = {0,0,0,0};
#pragma unroll 1
    for (int r = 0; r < 4; r++) {
        const float* tWr = tW + (size_t)r * 129 * NUx;
        const float* aWr = aW + (size_t)r * 129 * NUx;
        const float* hWr = hW + (size_t)r * 129 * NUx;
        u64 ft[2] = {0,0}, fa[2] = {0,0}, fh[2] = {0,0};
#pragma unroll 4
        for (int u = 0; u < 128; u++) {
            float wt = __ldg(tWr + u * NUx + n);
            float wa = __ldg(aWr + u * NUx + n);
            float wh = __ldg(hWr + u * NUx + n);
            u64 wt2 = pk2(wt, wt), wa2 = pk2(wa, wa), wh2 = pk2(wh, wh);
            ulonglong2 xt = *(const ulonglong2*)(sGT + u * 16 + iB);
            ulonglong2 xa = *(const ulonglong2*)(sGT + 2048 + u * 16 + iB);
            ulonglong2 xh = *(const ulonglong2*)(sGT + 2 * 2048 + u * 16 + iB);
            ft[0] = fma2(xt.x, wt2, ft[0]); ft[1] = fma2(xt.y, wt2, ft[1]);
            fa[0] = fma2(xa.x, wa2, fa[0]); fa[1] = fma2(xa.y, wa2, fa[1]);
            fh[0] = fma2(xh.x, wh2, fh[0]); fh[1] = fma2(xh.y, wh2, fh[1]);
        }
        float padT = __ldg(tWr + 128 * NUx + n);
        float padA = __ldg(aWr + 128 * NUx + n);
        float padH = __ldg(hWr + 128 * NUx + n);
        float wfr  = __ldg(Wf + r);
#pragma unroll
        for (int p = 0; p < 2; p++) {
            float2 t = up2(ft[p]), a = up2(fa[p]), h = up2(fh[p]);
            lga[2*p]   += wfr * (t.x + padT) * (a.x + padA) * (h.x + padH);
            lga[2*p+1] += wfr * (t.y + padT) * (a.y + padA) * (h.y + padH);
        }
    }
    {
        float bn = __ldg(bias + n);
#pragma unroll
        for (int j = 0; j < 4; j++) {
            float v = lga[j] + bn;
            g_lg[(size_t)(b0 + iB + j) * NUx + n] = v > 0.f ? v : 0.f;
        }
    }
}

// ---------------- k4: forget gate GEMM + h + h_tilde (one CTA per b) -------
// dyn smem: sW 128*128 | shT 128*68 (h_pre^T, padded) | spart 16*128 | misc
#define K4_SMEM_FLOATS (16384 + 8704 + 2048 + 64 + 128 + 128)

__global__ __launch_bounds__(256) void k4_main(
    const float* __restrict__ inputs, const float* __restrict__ states,
    const float* __restrict__ g3W, float* __restrict__ out_h) {
    extern __shared__ float sm4[];
    float* sW    = sm4;            // [128][128]
    float* shT   = sm4 + 16384;    // [128][68]  shT[k][m] = h_pre[m][k]
    float* spart = shT + 8704;     // [16][128]
    float* scorr = spart + 2048;   // 64
    float* slg   = scorr + 64;     // 128
    float* sbase = slg + 128;      // 128

    int tid = threadIdx.x, b = blockIdx.x;
    for (int idx = tid * 4; idx < 16384; idx += 1024)
        *(float4*)(sW + idx) = __ldg((const float4*)(g3W + idx));
    const float* hp = states + (size_t)b * MSx * NUx;
    for (int idx = tid; idx < MSx * NUx; idx += 256) {
        int m = idx >> 7, k = idx & 127;
        shT[k * 68 + m] = hp[idx];
    }
    if (tid < 64) scorr[tid] = inputs[(size_t)b * INC + NUx + tid];
    if (tid < 128) {
        slg[tid]   = g_lg[(size_t)b * NUx + tid];
        sbase[tid] = g_base[(size_t)b * NUx + tid];
    }
    __syncthreads();

    const int ty = tid >> 4, tx = tid & 15;
    const int m0 = ty * 4;
    const int na = tx * 4, nb = 64 + tx * 4;   // conflict-free LDS phases

    u64 base2[4] = { pk2(sbase[na], sbase[na+1]), pk2(sbase[na+2], sbase[na+3]),
                     pk2(sbase[nb], sbase[nb+1]), pk2(sbase[nb+2], sbase[nb+3]) };
    u64 acc[4][4];
#pragma unroll
    for (int mi = 0; mi < 4; mi++)
#pragma unroll
        for (int p = 0; p < 4; p++) acc[mi][p] = base2[p];

#pragma unroll 4
    for (int k = 0; k < 128; k++) {
        ulonglong2 w0 = *(const ulonglong2*)(sW + k * NUx + na);
        ulonglong2 w1 = *(const ulonglong2*)(sW + k * NUx + nb);
        float4 a4 = *(const float4*)(shT + k * 68 + m0);
        u64 wv[4] = {w0.x, w0.y, w1.x, w1.y};
        u64 a0 = pk2(a4.x, a4.x), a1 = pk2(a4.y, a4.y);
        u64 a2 = pk2(a4.z, a4.z), a3 = pk2(a4.w, a4.w);
        u64 av[4] = {a0, a1, a2, a3};
#pragma unroll
        for (int mi = 0; mi < 4; mi++)
#pragma unroll
            for (int p = 0; p < 4; p++) acc[mi][p] = fma2(av[mi], wv[p], acc[mi][p]);
    }

    // epilogue: fg = sigmoid(acc); h = h_pre*fg + corr[m]*lg[n]; reduce corr.h
    float cr[4] = {scorr[m0], scorr[m0+1], scorr[m0+2], scorr[m0+3]};
    float lgv[8] = {slg[na], slg[na+1], slg[na+2], slg[na+3],
                    slg[nb], slg[nb+1], slg[nb+2], slg[nb+3]};
    float pt[8] = {0,0,0,0,0,0,0,0};
    float* ob = out_h + (size_t)b * MSx * NUx;

    // h_pre values for epilogue: h_pre[m0+mi][n] = shT[n][m0+mi]
    float hhA[4][4], hhB[4][4];
#pragma unroll
    for (int q = 0; q < 4; q++) {
        float4 va = *(const float4*)(shT + (na + q) * 68 + m0);
        float4 vb = *(const float4*)(shT + (nb + q) * 68 + m0);
        hhA[q][0] = va.x; hhA[q][1] = va.y; hhA[q][2] = va.z; hhA[q][3] = va.w;
        hhB[q][0] = vb.x; hhB[q][1] = vb.y; hhB[q][2] = vb.z; hhB[q][3] = vb.w;
    }

#pragma unroll
    for (int mi = 0; mi < 4; mi++) {
        float z[8];
#pragma unroll
        for (int p = 0; p < 4; p++) {
            float2 f = up2(acc[mi][p]);
            z[2*p] = f.x; z[2*p+1] = f.y;
        }
        float hv[8];
#pragma unroll
        for (int q = 0; q < 4; q++) {
            float fg = sigf(z[q]);
            hv[q] = hhA[q][mi] * fg + cr[mi] * lgv[q];
            pt[q] += cr[mi] * hv[q];
        }
#pragma unroll
        for (int q = 0; q < 4; q++) {
            float fg = sigf(z[4 + q]);
            hv[4+q] = hhB[q][mi] * fg + cr[mi] * lgv[4 + q];
            pt[4+q] += cr[mi] * hv[4+q];
        }
        *(float4*)(ob + (m0 + mi) * NUx + na) = make_float4(hv[0], hv[1], hv[2], hv[3]);
        *(float4*)(ob + (m0 + mi) * NUx + nb) = make_float4(hv[4], hv[5], hv[6], hv[7]);
    }
#pragma unroll
    for (int q = 0; q < 4; q++) {
        spart[ty * NUx + na + q] = pt[q];
        spart[ty * NUx + nb + q] = pt[4 + q];
    }
    __syncthreads();
    if (tid < 128) {
        float s = 0.f;
#pragma unroll
        for (int t = 0; t < 16; t++) s += spart[t * NUx + tid];
        g_htilde[(size_t)b * NUx + tid] = s;
    }
}

// ---------------- k5: after_preds + improve -> result ----------------------
__global__ __launch_bounds__(512) void k5_result(
    const float* __restrict__ inputs, const float* __restrict__ outW,
    const float* __restrict__ outb, float* __restrict__ out) {
    __shared__ __align__(16) float sA[256 * 16];  // rows 0..127 htilde, 128..255 topic
    __shared__ float sAfter[16];
    int tid = threadIdx.x;
    int b0 = blockIdx.x * 16;
    for (int idx = tid; idx < 16 * 128; idx += 512) {
        int i = idx >> 7, n = idx & 127;
        size_t ib = (size_t)(b0 + i);
        sA[n * 16 + i]         = g_htilde[ib * NUx + n];
        sA[(128 + n) * 16 + i] = inputs[ib * INC + 192 + n];
    }
    if (tid < 16) sAfter[tid] = 0.f;
    __syncthreads();

    const int i2 = tid >> 7, n = tid & 127, iB = i2 * 4;
    u64 zp[2] = {0,0};
#pragma unroll 4
    for (int u = 0; u < 256; u++) {
        float w = __ldg(outW + u * NUx + n);
        u64 w2 = pk2(w, w);
        ulonglong2 x = *(const ulonglong2*)(sA + u * 16 + iB);
        zp[0] = fma2(x.x, w2, zp[0]);
        zp[1] = fma2(x.y, w2, zp[1]);
    }
    float ob = __ldg(outb + n);
    float pj[4];
    {
        float2 P0 = up2(zp[0]), P1 = up2(zp[1]);
        pj[0] = sigf(P0.x + ob); pj[1] = sigf(P0.y + ob);
        pj[2] = sigf(P1.x + ob); pj[3] = sigf(P1.y + ob);
    }
#pragma unroll
    for (int j = 0; j < 4; j++) {
        float v = pj[j];
#pragma unroll
        for (int off = 16; off > 0; off >>= 1)
            v += __shfl_xor_sync(0xFFFFFFFFu, v, off);
        if ((tid & 31) == 0) atomicAdd(&sAfter[iB + j], v);
    }
    __syncthreads();
    if (tid < 16) {
        int b = b0 + tid;
        float after = sAfter[tid] * (1.f / 128.f);
        float p = g_preds[b];
        out[2 * b]     = p;
        out[2 * b + 1] = (after - p) / (1.f - p);
    }
}

// ---------------- launch ----------------------------------------------------
extern "C" void kernel_launch(void* const* d_in, const int* in_sizes, int n_in,
                              void* d_out, int out_size) {
    const float* inputs = (const float*)d_in[0];
    const float* states = (const float*)d_in[1];
    const float* tW     = (const float*)d_in[2];
    const float* aW     = (const float*)d_in[3];
    const float* hW     = (const float*)d_in[4];
    const float* Wf     = (const float*)d_in[5];
    const float* bias   = (const float*)d_in[6];
    const float* g3W    = (const float*)d_in[7];
    const float* g3b    = (const float*)d_in[8];
    const float* outW   = (const float*)d_in[9];
    const float* outb   = (const float*)d_in[10];
    const float* tgW    = (const float*)d_in[11];
    const float* tgb    = (const float*)d_in[12];
    const float* agW    = (const float*)d_in[13];
    const float* agb    = (const float*)d_in[14];
    const float* hgW    = (const float*)d_in[15];
    const float* hgb    = (const float*)d_in[16];

    int B = in_sizes[0] / INC;  // 4096
    float* out   = (float*)d_out;
    float* out_h = out + (size_t)2 * B;  // (result, h) flattened in tuple order

    const int smem2 = K2_SMEM_FLOATS * (int)sizeof(float);
    const int smem4 = K4_SMEM_FLOATS * (int)sizeof(float);
    cudaFuncSetAttribute(k2_gates, cudaFuncAttributeMaxDynamicSharedMemorySize, smem2);
    cudaFuncSetAttribute(k4_main, cudaFuncAttributeMaxDynamicSharedMemorySize, smem4);

    k0_sums<<<1, 128>>>(g3W);
    k1_hpt<<<B, 256>>>(inputs, states);
    k2_gates<<<B / 16, 512, smem2>>>(inputs, tgW, tgb, agW, agb, hgW, hgb,
                                     outW, outb, g3W, g3b, tW, aW, hW, Wf, bias);
    k4_main<<<B, 256, smem4>>>(inputs, states, g3W, out_h);
    k5_result<<<B / 16, 512>>>(inputs, outW, outb, out);
}

// round 15
// speedup vs baseline: 2.6189x; 1.0706x over previous
#include <cuda_runtime.h>
#include <math.h>

#define NUx 128
#define MSx 64
#define INC 323      // inputs row stride: NU + MS + DT + 3
#define BMAX 4096
#define BN (BMAX * NUx)

typedef unsigned long long u64;

// ---------------- scratch (device globals: no allocation allowed) ----------
__device__ float g_hpt[BN];      // h_pre_tilde
__device__ float g_base[BN];     // per-b part of gate3 pre-activation
__device__ float g_lg[BN];       // learning gain
__device__ float g_preds[BMAX];  // preds (already /128)
__device__ float g_htilde[BN];   // corr . h
__device__ float g_S[3 * NUx];   // column sums of gate3_W rows 256..405

__device__ __forceinline__ float sigf(float x) { return 1.f / (1.f + __expf(-x)); }
__device__ __forceinline__ float gainf(float f) {
    return 0.3f + 0.7f / (1.f + __expf(-10.f * (f - 0.3f)));
}

// ---- packed f32x2 helpers (sm_103a FFMA2) ----------------------------------
__device__ __forceinline__ u64 pk2(float lo, float hi) {
    u64 r; asm("mov.b64 %0, {%1, %2};" : "=l"(r) : "f"(lo), "f"(hi)); return r;
}
__device__ __forceinline__ float2 up2(u64 v) {
    float2 f; asm("mov.b64 {%0, %1}, %2;" : "=f"(f.x), "=f"(f.y) : "l"(v)); return f;
}
__device__ __forceinline__ u64 fma2(u64 a, u64 b, u64 c) {
    u64 d; asm("fma.rn.f32x2 %0, %1, %2, %3;" : "=l"(d) : "l"(a), "l"(b), "l"(c)); return d;
}

// batch-index swizzle for 32-wide transposed smem tiles (kills STS conflicts;
// compute-side reads are uniform per warp so the swizzle costs nothing there)
__device__ __forceinline__ int SWZ(int n, int i) {
    return n * 32 + (i ^ ((n & 3) << 3));
}

// ---------------- k0: fold the 3x50 broadcast rows of gate3_W --------------
__global__ void k0_sums(const float* __restrict__ g3W) {
    int n = threadIdx.x;  // 128 threads
    float s0 = 0.f, s1 = 0.f, s2 = 0.f;
#pragma unroll
    for (int u = 0; u < 50; u++) {
        s0 += g3W[(256 + u) * NUx + n];
        s1 += g3W[(306 + u) * NUx + n];
        s2 += g3W[(356 + u) * NUx + n];
    }
    g_S[n] = s0; g_S[NUx + n] = s1; g_S[2 * NUx + n] = s2;
}

// ---------------- k1: h_pre_tilde[b][n] = sum_m corr[m]*h_pre[m][n] --------
__global__ __launch_bounds__(256) void k1_hpt(const float* __restrict__ inputs,
                                              const float* __restrict__ states) {
    int b = blockIdx.x;
    int tid = threadIdx.x;
    int n = tid & 127, half = tid >> 7;  // half in {0,1}, m-range of 32
    __shared__ float sc[MSx];
    __shared__ float sp[2 * NUx];
    if (tid < MSx) sc[tid] = inputs[(size_t)b * INC + NUx + tid];
    __syncthreads();
    const float* hp = states + (size_t)b * MSx * NUx + (size_t)half * 32 * NUx;
    const float* cm = sc + half * 32;
    float acc = 0.f;
#pragma unroll 8
    for (int m = 0; m < 32; m++) acc += cm[m] * hp[(size_t)m * NUx + n];
    sp[half * NUx + n] = acc;
    __syncthreads();
    if (tid < NUx) g_hpt[(size_t)b * NUx + tid] = sp[tid] + sp[NUx + tid];
}

// ---------------- k2: gates + preds + base + fusion (32-batch, 512 thr) ----
// dyn smem floats: sAT 384*32 | sGT 3*128*32 | sTAH 96 | sGain 96 | sPred 32
#define K2_SMEM_FLOATS (12288 + 12288 + 96 + 96 + 32)

__global__ __launch_bounds__(512) void k2_gates(
    const float* __restrict__ inputs,
    const float* __restrict__ tgW, const float* __restrict__ tgb,
    const float* __restrict__ agW, const float* __restrict__ agb,
    const float* __restrict__ hgW, const float* __restrict__ hgb,
    const float* __restrict__ outW, const float* __restrict__ outb,
    const float* __restrict__ g3W, const float* __restrict__ g3b,
    const float* __restrict__ tW, const float* __restrict__ aW,
    const float* __restrict__ hW,
    const float* __restrict__ Wf, const float* __restrict__ bias) {
    extern __shared__ float sm[];
    float* sAT   = sm;              // [384][32] swizzled
    float* sGT   = sm + 12288;      // [3][128][32] swizzled
    float* sTAH  = sGT + 12288;     // [32][3]
    float* sGain = sTAH + 96;       // [32][3]
    float* sPred = sGain + 96;      // [32]

    int tid = threadIdx.x;
    int b0 = blockIdx.x * 32;

    for (int idx = tid; idx < 32 * 128; idx += 512) {
        int i = idx >> 7, n = idx & 127;   // lanes: consecutive n -> coalesced
        size_t ib = (size_t)(b0 + i);
        sAT[SWZ(n, i)]       = g_hpt[ib * NUx + n];
        sAT[SWZ(128 + n, i)] = inputs[ib * INC + n];
        sAT[SWZ(256 + n, i)] = inputs[ib * INC + 192 + n];
    }
    if (tid < 32) {
        size_t ib = (size_t)(b0 + tid);
        float t = inputs[ib * INC + 320];
        float a = inputs[ib * INC + 321];
        float h = inputs[ib * INC + 322];
        sTAH[tid * 3 + 0] = t; sTAH[tid * 3 + 1] = a; sTAH[tid * 3 + 2] = h;
        sGain[tid * 3 + 0] = gainf(t);
        sGain[tid * 3 + 1] = gainf(a);
        sGain[tid * 3 + 2] = gainf(h);
        sPred[tid] = 0.f;
    }
    __syncthreads();

    const int i2 = tid >> 7;      // 0..3
    const int n  = tid & 127;
    const int iB = i2 * 8;        // 8 batch rows per thread

    // ---- pass A1: three gate matvecs (f32x2, 8 rows/thread) ----
    u64 zt[4] = {0,0,0,0}, za[4] = {0,0,0,0}, zh[4] = {0,0,0,0};
#pragma unroll 4
    for (int u = 0; u < 256; u++) {
        float wt = __ldg(tgW + u * NUx + n);
        float wa = __ldg(agW + u * NUx + n);
        float wh = __ldg(hgW + u * NUx + n);
        u64 wt2 = pk2(wt, wt), wa2 = pk2(wa, wa), wh2 = pk2(wh, wh);
        int xo = SWZ(u, iB);
        ulonglong2 xlo = *(const ulonglong2*)(sAT + xo);
        ulonglong2 xhi = *(const ulonglong2*)(sAT + xo + 4);
        u64 xv[4] = {xlo.x, xlo.y, xhi.x, xhi.y};
#pragma unroll
        for (int p = 0; p < 4; p++) {
            zt[p] = fma2(xv[p], wt2, zt[p]);
            za[p] = fma2(xv[p], wa2, za[p]);
            zh[p] = fma2(xv[p], wh2, zh[p]);
        }
    }
    {
        float tb = __ldg(tgb + n), ab = __ldg(agb + n), hb = __ldg(hgb + n);
#pragma unroll
        for (int p = 0; p < 4; p++) {
            float2 t = up2(zt[p]), a = up2(za[p]), h = up2(zh[p]);
            int i0 = iB + 2 * p, i1 = i0 + 1;
            sGT[SWZ(n, i0)]            = sigf((t.x + tb) * sGain[i0 * 3 + 0]);
            sGT[SWZ(n, i1)]            = sigf((t.y + tb) * sGain[i1 * 3 + 0]);
            sGT[4096 + SWZ(n, i0)]     = sigf((a.x + ab) * sGain[i0 * 3 + 1]);
            sGT[4096 + SWZ(n, i1)]     = sigf((a.y + ab) * sGain[i1 * 3 + 1]);
            sGT[2 * 4096 + SWZ(n, i0)] = sigf((h.x + hb) * sGain[i0 * 3 + 2]);
            sGT[2 * 4096 + SWZ(n, i1)] = sigf((h.y + hb) * sGain[i1 * 3 + 2]);
        }
    }

    // ---- pass A2: preds pre-activation + gate3 per-b base ----
    u64 zp[4] = {0,0,0,0}, zb[4] = {0,0,0,0};
#pragma unroll 4
    for (int u = 0; u < 128; u++) {
        float wp1 = __ldg(outW + u * NUx + n);
        float wp2 = __ldg(outW + (128 + u) * NUx + n);
        float wb  = __ldg(g3W + (128 + u) * NUx + n);
        u64 wp12 = pk2(wp1, wp1), wp22 = pk2(wp2, wp2), wb2 = pk2(wb, wb);
        int xo = SWZ(u, iB);
        ulonglong2 h01 = *(const ulonglong2*)(sAT + xo);
        ulonglong2 h23 = *(const ulonglong2*)(sAT + xo + 4);
        ulonglong2 i01 = *(const ulonglong2*)(sAT + 4096 + xo);
        ulonglong2 i23 = *(const ulonglong2*)(sAT + 4096 + xo + 4);
        ulonglong2 t01 = *(const ulonglong2*)(sAT + 8192 + xo);
        ulonglong2 t23 = *(const ulonglong2*)(sAT + 8192 + xo + 4);
        u64 xh[4] = {h01.x, h01.y, h23.x, h23.y};
        u64 xi[4] = {i01.x, i01.y, i23.x, i23.y};
        u64 xt[4] = {t01.x, t01.y, t23.x, t23.y};
#pragma unroll
        for (int p = 0; p < 4; p++) {
            zp[p] = fma2(xh[p], wp12, zp[p]);
            zp[p] = fma2(xt[p], wp22, zp[p]);
            zb[p] = fma2(xi[p], wb2,  zb[p]);
        }
    }
    {
        float ob = __ldg(outb + n), gb = __ldg(g3b + n);
        float S0 = g_S[n], S1 = g_S[NUx + n], S2 = g_S[2 * NUx + n];
        float pj[8];
#pragma unroll
        for (int p = 0; p < 4; p++) {
            float2 P = up2(zp[p]), Bv = up2(zb[p]);
            int i0 = iB + 2 * p, i1 = i0 + 1;
            size_t r0 = (size_t)(b0 + i0) * NUx + n;
            size_t r1 = (size_t)(b0 + i1) * NUx + n;
            g_base[r0] = Bv.x + gb + sTAH[i0*3+0]*S0 + sTAH[i0*3+1]*S1 + sTAH[i0*3+2]*S2;
            g_base[r1] = Bv.y + gb + sTAH[i1*3+0]*S0 + sTAH[i1*3+1]*S1 + sTAH[i1*3+2]*S2;
            pj[2*p]   = sigf(P.x + ob);
            pj[2*p+1] = sigf(P.y + ob);
        }
#pragma unroll
        for (int j = 0; j < 8; j++) {
            float v = pj[j];
#pragma unroll
            for (int off = 16; off > 0; off >>= 1)
                v += __shfl_xor_sync(0xFFFFFFFFu, v, off);
            if ((tid & 31) == 0) atomicAdd(&sPred[iB + j], v);
        }
    }
    __syncthreads();
    if (tid < 32) g_preds[b0 + tid] = sPred[tid] * (1.f / 128.f);

    // ---- pass B: R=4 three-way fusion -> learning gain ----
    float lga[8] = {0,0,0,0,0,0,0,0};
#pragma unroll 1
    for (int r = 0; r < 4; r++) {
        const float* tWr = tW + (size_t)r * 129 * NUx;
        const float* aWr = aW + (size_t)r * 129 * NUx;
        const float* hWr = hW + (size_t)r * 129 * NUx;
        u64 ft[4] = {0,0,0,0}, fa[4] = {0,0,0,0}, fh[4] = {0,0,0,0};
#pragma unroll 4
        for (int u = 0; u < 128; u++) {
            float wt = __ldg(tWr + u * NUx + n);
            float wa = __ldg(aWr + u * NUx + n);
            float wh = __ldg(hWr + u * NUx + n);
            u64 wt2 = pk2(wt, wt), wa2 = pk2(wa, wa), wh2 = pk2(wh, wh);
            int xo = SWZ(u, iB);
            ulonglong2 t01 = *(const ulonglong2*)(sGT + xo);
            ulonglong2 t23 = *(const ulonglong2*)(sGT + xo + 4);
            ulonglong2 a01 = *(const ulonglong2*)(sGT + 4096 + xo);
            ulonglong2 a23 = *(const ulonglong2*)(sGT + 4096 + xo + 4);
            ulonglong2 h01 = *(const ulonglong2*)(sGT + 2 * 4096 + xo);
            ulonglong2 h23 = *(const ulonglong2*)(sGT + 2 * 4096 + xo + 4);
            u64 xt[4] = {t01.x, t01.y, t23.x, t23.y};
            u64 xa[4] = {a01.x, a01.y, a23.x, a23.y};
            u64 xh[4] = {h01.x, h01.y, h23.x, h23.y};
#pragma unroll
            for (int p = 0; p < 4; p++) {
                ft[p] = fma2(xt[p], wt2, ft[p]);
                fa[p] = fma2(xa[p], wa2, fa[p]);
                fh[p] = fma2(xh[p], wh2, fh[p]);
            }
        }
        float padT = __ldg(tWr + 128 * NUx + n);
        float padA = __ldg(aWr + 128 * NUx + n);
        float padH = __ldg(hWr + 128 * NUx + n);
        float wfr  = __ldg(Wf + r);
#pragma unroll
        for (int p = 0; p < 4; p++) {
            float2 t = up2(ft[p]), a = up2(fa[p]), h = up2(fh[p]);
            lga[2*p]   += wfr * (t.x + padT) * (a.x + padA) * (h.x + padH);
            lga[2*p+1] += wfr * (t.y + padT) * (a.y + padA) * (h.y + padH);
        }
    }
    {
        float bn = __ldg(bias + n);
#pragma unroll
        for (int j = 0; j < 8; j++) {
            float v = lga[j] + bn;
            g_lg[(size_t)(b0 + iB + j) * NUx + n] = v > 0.f ? v : 0.f;
        }
    }
}

// ---------------- k4: forget gate GEMM + h + h_tilde (2 b per CTA) ---------
// dyn smem: sW 128*128 | sH 64*128 natural | spart 16*128 | misc (2 b's)
#define K4_SMEM_FLOATS (16384 + 8192 + 2048 + 128 + 256 + 256)

__global__ __launch_bounds__(256) void k4_main(
    const float* __restrict__ inputs, const float* __restrict__ states,
    const float* __restrict__ g3W, float* __restrict__ out_h) {
    extern __shared__ float sm4[];
    float* sW    = sm4;            // [128][128]
    float* sH    = sm4 + 16384;    // [64][128]  natural layout
    float* spart = sH + 8192;      // [16][128]
    float* scorr = spart + 2048;   // [2][64]
    float* slg   = scorr + 128;    // [2][128]
    float* sbase = slg + 256;      // [2][128]

    int tid = threadIdx.x;
    int bb = blockIdx.x * 2;

    // stage weights ONCE per CTA
    for (int idx = tid * 4; idx < 16384; idx += 1024)
        *(float4*)(sW + idx) = __ldg((const float4*)(g3W + idx));
    // per-b vectors for both b's
    if (tid < 128) {
        int ib = tid >> 6, mm = tid & 63;
        scorr[tid] = inputs[(size_t)(bb + ib) * INC + NUx + mm];
    }
    {
        int ib = tid >> 7, n = tid & 127;
        slg[tid]   = g_lg[(size_t)(bb + ib) * NUx + n];
        sbase[tid] = g_base[(size_t)(bb + ib) * NUx + n];
    }

    const int ty = tid >> 4, tx = tid & 15;
    const int m0 = ty * 4;
    const int na = tx * 4, nb = 64 + tx * 4;

    for (int ib = 0; ib < 2; ib++) {
        int b = bb + ib;
        __syncthreads();  // sH/spart free (covers initial staging on ib=0)
        const float* hp = states + (size_t)b * MSx * NUx;
        for (int idx = tid * 4; idx < 8192; idx += 1024)
            *(float4*)(sH + idx) = *(const float4*)(hp + idx);
        __syncthreads();

        u64 base2[4] = { pk2(sbase[ib*128+na],   sbase[ib*128+na+1]),
                         pk2(sbase[ib*128+na+2], sbase[ib*128+na+3]),
                         pk2(sbase[ib*128+nb],   sbase[ib*128+nb+1]),
                         pk2(sbase[ib*128+nb+2], sbase[ib*128+nb+3]) };
        u64 acc[4][4];
#pragma unroll
        for (int mi = 0; mi < 4; mi++)
#pragma unroll
            for (int p = 0; p < 4; p++) acc[mi][p] = base2[p];

#pragma unroll 2
        for (int k0 = 0; k0 < 128; k0 += 4) {
            float am[4][4];
#pragma unroll
            for (int mi = 0; mi < 4; mi++) {
                float4 a4 = *(const float4*)(sH + (m0 + mi) * NUx + k0);
                am[mi][0] = a4.x; am[mi][1] = a4.y; am[mi][2] = a4.z; am[mi][3] = a4.w;
            }
#pragma unroll
            for (int kk = 0; kk < 4; kk++) {
                const float* wr = sW + (k0 + kk) * NUx;
                ulonglong2 w0 = *(const ulonglong2*)(wr + na);
                ulonglong2 w1 = *(const ulonglong2*)(wr + nb);
                u64 wv[4] = {w0.x, w0.y, w1.x, w1.y};
#pragma unroll
                for (int mi = 0; mi < 4; mi++) {
                    u64 aa = pk2(am[mi][kk], am[mi][kk]);
#pragma unroll
                    for (int p = 0; p < 4; p++)
                        acc[mi][p] = fma2(aa, wv[p], acc[mi][p]);
                }
            }
        }

        // epilogue: fg = sigmoid(acc); h = h_pre*fg + corr[m]*lg[n]
        float cr[4] = {scorr[ib*64+m0], scorr[ib*64+m0+1],
                       scorr[ib*64+m0+2], scorr[ib*64+m0+3]};
        float lgv[8] = {slg[ib*128+na], slg[ib*128+na+1], slg[ib*128+na+2], slg[ib*128+na+3],
                        slg[ib*128+nb], slg[ib*128+nb+1], slg[ib*128+nb+2], slg[ib*128+nb+3]};
        float pt[8] = {0,0,0,0,0,0,0,0};
        float* ob = out_h + (size_t)b * MSx * NUx;

#pragma unroll
        for (int mi = 0; mi < 4; mi++) {
            float4 ha  = *(const float4*)(sH + (m0 + mi) * NUx + na);
            float4 hb4 = *(const float4*)(sH + (m0 + mi) * NUx + nb);
            float hpv[8] = {ha.x, ha.y, ha.z, ha.w, hb4.x, hb4.y, hb4.z, hb4.w};
            float z[8];
#pragma unroll
            for (int p = 0; p < 4; p++) {
                float2 f = up2(acc[mi][p]);
                z[2*p] = f.x; z[2*p+1] = f.y;
            }
            float hv[8];
#pragma unroll
            for (int q = 0; q < 8; q++) {
                float fg = sigf(z[q]);
                hv[q] = hpv[q] * fg + cr[mi] * lgv[q];
                pt[q] += cr[mi] * hv[q];
            }
            *(float4*)(ob + (m0 + mi) * NUx + na) = make_float4(hv[0], hv[1], hv[2], hv[3]);
            *(float4*)(ob + (m0 + mi) * NUx + nb) = make_float4(hv[4], hv[5], hv[6], hv[7]);
        }
#pragma unroll
        for (int q = 0; q < 4; q++) {
            spart[ty * NUx + na + q] = pt[q];
            spart[ty * NUx + nb + q] = pt[4 + q];
        }
        __syncthreads();
        if (tid < 128) {
            float s = 0.f;
#pragma unroll
            for (int t = 0; t < 16; t++) s += spart[t * NUx + tid];
            g_htilde[(size_t)b * NUx + tid] = s;
        }
    }
}

// ---------------- k5: after_preds + improve -> result ----------------------
__global__ __launch_bounds__(512) void k5_result(
    const float* __restrict__ inputs, const float* __restrict__ outW,
    const float* __restrict__ outb, float* __restrict__ out) {
    __shared__ __align__(16) float sA[256 * 16];  // rows 0..127 htilde, 128..255 topic
    __shared__ float sAfter[16];
    int tid = threadIdx.x;
    int b0 = blockIdx.x * 16;
    for (int idx = tid; idx < 16 * 128; idx += 512) {
        int i = idx >> 7, n = idx & 127;
        size_t ib = (size_t)(b0 + i);
        sA[n * 16 + i]         = g_htilde[ib * NUx + n];
        sA[(128 + n) * 16 + i] = inputs[ib * INC + 192 + n];
    }
    if (tid < 16) sAfter[tid] = 0.f;
    __syncthreads();

    const int i2 = tid >> 7, n = tid & 127, iB = i2 * 4;
    u64 zp[2] = {0,0};
#pragma unroll 4
    for (int u = 0; u < 256; u++) {
        float w = __ldg(outW + u * NUx + n);
        u64 w2 = pk2(w, w);
        ulonglong2 x = *(const ulonglong2*)(sA + u * 16 + iB);
        zp[0] = fma2(x.x, w2, zp[0]);
        zp[1] = fma2(x.y, w2, zp[1]);
    }
    float ob = __ldg(outb + n);
    float pj[4];
    {
        float2 P0 = up2(zp[0]), P1 = up2(zp[1]);
        pj[0] = sigf(P0.x + ob); pj[1] = sigf(P0.y + ob);
        pj[2] = sigf(P1.x + ob); pj[3] = sigf(P1.y + ob);
    }
#pragma unroll
    for (int j = 0; j < 4; j++) {
        float v = pj[j];
#pragma unroll
        for (int off = 16; off > 0; off >>= 1)
            v += __shfl_xor_sync(0xFFFFFFFFu, v, off);
        if ((tid & 31) == 0) atomicAdd(&sAfter[iB + j], v);
    }
    __syncthreads();
    if (tid < 16) {
        int b = b0 + tid;
        float after = sAfter[tid] * (1.f / 128.f);
        float p = g_preds[b];
        out[2 * b]     = p;
        out[2 * b + 1] = (after - p) / (1.f - p);
    }
}

// ---------------- launch ----------------------------------------------------
extern "C" void kernel_launch(void* const* d_in, const int* in_sizes, int n_in,
                              void* d_out, int out_size) {
    const float* inputs = (const float*)d_in[0];
    const float* states = (const float*)d_in[1];
    const float* tW     = (const float*)d_in[2];
    const float* aW     = (const float*)d_in[3];
    const float* hW     = (const float*)d_in[4];
    const float* Wf     = (const float*)d_in[5];
    const float* bias   = (const float*)d_in[6];
    const float* g3W    = (const float*)d_in[7];
    const float* g3b    = (const float*)d_in[8];
    const float* outW   = (const float*)d_in[9];
    const float* outb   = (const float*)d_in[10];
    const float* tgW    = (const float*)d_in[11];
    const float* tgb    = (const float*)d_in[12];
    const float* agW    = (const float*)d_in[13];
    const float* agb    = (const float*)d_in[14];
    const float* hgW    = (const float*)d_in[15];
    const float* hgb    = (const float*)d_in[16];

    int B = in_sizes[0] / INC;  // 4096
    float* out   = (float*)d_out;
    float* out_h = out + (size_t)2 * B;  // (result, h) flattened in tuple order

    const int smem2 = K2_SMEM_FLOATS * (int)sizeof(float);
    const int smem4 = K4_SMEM_FLOATS * (int)sizeof(float);
    cudaFuncSetAttribute(k2_gates, cudaFuncAttributeMaxDynamicSharedMemorySize, smem2);
    cudaFuncSetAttribute(k4_main, cudaFuncAttributeMaxDynamicSharedMemorySize, smem4);

    k0_sums<<<1, 128>>>(g3W);
    k1_hpt<<<B, 256>>>(inputs, states);
    k2_gates<<<B / 32, 512, smem2>>>(inputs, tgW, tgb, agW, agb, hgW, hgb,
                                     outW, outb, g3W, g3b, tW, aW, hW, Wf, bias);
    k4_main<<<B / 2, 256, smem4>>>(inputs, states, g3W, out_h);
    k5_result<<<B / 16, 512>>>(inputs, outW, outb, out);
}